// round 2
// baseline (speedup 1.0000x reference)
#include <cuda_runtime.h>
#include <cuda_bf16.h>
#include <math.h>

// Problem constants
#define BB 16
#define TT 2000
#define CC 1536
#define NH 8
#define DD 192
#define QQ 256
#define AA 192
#define TTILE 16

// ---------------- scratch (device globals: no allocations allowed) --------
__device__ float g_c[BB * CC * 2];                 // interleaved mean/std per (b,ch)
__device__ float g_hck[BB * NH * QQ];              // head_ck
__device__ float g_ckdot[BB * NH];                 // sum_q head_ck*vck
__device__ float g_qdot[NH];                       // sum_{q,a} query*vhq
__device__ float g_hcq[(size_t)BB * NH * QQ * AA]; // head_cq / sqrt(Q)
__device__ float g_scores[(size_t)BB * TT * NH * AA]; // [b][t][n][a]

// ---------------- K1: mean/std over time ----------------------------------
__global__ void k_stats(const float* __restrict__ ht) {
    int b = blockIdx.y;
    int ch = blockIdx.x * 128 + threadIdx.x;
    int ty = threadIdx.y;
    float s = 0.f, s2 = 0.f;
    const float* p = ht + (size_t)b * TT * CC + ch;
    for (int t = ty; t < TT; t += 8) {
        float v = p[(size_t)t * CC];
        s += v; s2 += v * v;
    }
    __shared__ float sh0[8][128];
    __shared__ float sh1[8][128];
    sh0[ty][threadIdx.x] = s;
    sh1[ty][threadIdx.x] = s2;
    __syncthreads();
    if (ty == 0) {
        for (int j = 1; j < 8; j++) { s += sh0[j][threadIdx.x]; s2 += sh1[j][threadIdx.x]; }
        float mean = s * (1.f / TT);
        float var = (s2 - (float)TT * mean * mean) * (1.f / (TT - 1));
        float sd = sqrtf(fmaxf(var, 0.f));
        g_c[((size_t)b * CC + ch) * 2 + 0] = mean;
        g_c[((size_t)b * CC + ch) * 2 + 1] = sd;
    }
}

// ---------------- K0: qdot[n] = sum_{q,a} query[n,q,a]*vhq[n,a,q] ---------
__global__ void k_qdot(const float* __restrict__ query, const float* __restrict__ vhq) {
    int n = blockIdx.x;
    int tid = threadIdx.x;
    float acc = 0.f;
    for (int i = tid; i < AA * QQ; i += 256) {
        int a = i >> 8, q = i & 255;
        acc += query[(n * QQ + q) * AA + a] * vhq[n * AA * QQ + i];
    }
    __shared__ float red[256];
    red[tid] = acc;
    __syncthreads();
    for (int off = 128; off > 0; off >>= 1) {
        if (tid < off) red[tid] += red[tid + off];
        __syncthreads();
    }
    if (tid == 0) g_qdot[n] = red[0];
}

// ---------------- K2: per-(b,n) context computations ----------------------
__global__ void k_context(const float* __restrict__ uk_W, const float* __restrict__ u_q1W,
                          const float* __restrict__ u_q2, const float* __restrict__ query,
                          const float* __restrict__ vcq, const float* __restrict__ vck,
                          const float* __restrict__ u_q1b,
                          const float* __restrict__ bnc_g, const float* __restrict__ bnc_b,
                          const float* __restrict__ bnc_m, const float* __restrict__ bnc_v) {
    int bn = blockIdx.x;
    int b = bn >> 3, n = bn & 7;
    int tid = threadIdx.x;
    __shared__ float c_sh[2 * DD];
    __shared__ float t1_sh[QQ];
    __shared__ float cq2_sh[AA];
    __shared__ float red[256];
    __shared__ float lamq_sh;

    // interleaved [mean,std] slice for this (b,n): contiguous 384 floats
    // NOTE: 2*DD = 384 > blockDim (256) -> must grid-stride, not mask!
    for (int i = tid; i < 2 * DD; i += 256)
        c_sh[i] = g_c[((size_t)b * CC + n * DD) * 2 + i];
    __syncthreads();

    // head_ck and cq1 path (tid == q)
    float hck = 0.f, cq1 = 0.f;
    {
        const float* uk = uk_W + n * (2 * DD) * QQ + tid;
        const float* u1 = u_q1W + n * (2 * DD) * QQ + tid;
        for (int l = 0; l < 2 * DD; l++) {
            float cv = c_sh[l];
            hck += cv * uk[(size_t)l * QQ];
            cq1 += cv * u1[(size_t)l * QQ];
        }
        g_hck[(size_t)bn * QQ + tid] = hck;
        cq1 += u_q1b[n * QQ + tid];
        float r = fmaxf(cq1, 0.f);
        float bnv = bnc_g[tid] * (r - bnc_m[tid]) * rsqrtf(bnc_v[tid] + 1e-5f) + bnc_b[tid];
        t1_sh[tid] = tanhf(bnv);
    }
    __syncthreads();

    // cq2[a] = sum_m t1[m] * u_q2[n,m,a]
    if (tid < AA) {
        float a2 = 0.f;
        const float* u2 = u_q2 + (size_t)n * QQ * AA + tid;
        for (int m = 0; m < QQ; m++) a2 += t1_sh[m] * u2[(size_t)m * AA];
        cq2_sh[tid] = a2;
    }
    __syncthreads();

    // vcqdot = sum_{a,q} cq2[a]*vcq[n,a,q]
    float acc = 0.f;
    for (int i = tid; i < AA * QQ; i += 256) {
        int a = i >> 8;
        acc += cq2_sh[a] * vcq[(size_t)n * AA * QQ + i];
    }
    red[tid] = acc;
    __syncthreads();
    for (int off = 128; off > 0; off >>= 1) {
        if (tid < off) red[tid] += red[tid + off];
        __syncthreads();
    }
    float vcqdot = red[0];
    __syncthreads();

    // ckdot = sum_q hck[q]*vck[n,q]
    red[tid] = hck * vck[n * QQ + tid];
    __syncthreads();
    for (int off = 128; off > 0; off >>= 1) {
        if (tid < off) red[tid] += red[tid + off];
        __syncthreads();
    }
    if (tid == 0) {
        g_ckdot[bn] = red[0];
        lamq_sh = 1.f / (1.f + expf(-(g_qdot[n] + vcqdot)));
    }
    __syncthreads();

    float lq = lamq_sh;
    const float inv_sq = 1.f / 16.f;  // 1/sqrt(Q)
    for (int i = tid; i < QQ * AA; i += 256) {
        int a = i % AA;
        g_hcq[(size_t)bn * QQ * AA + i] =
            ((1.f - lq) * query[(size_t)n * QQ * AA + i] + lq * cq2_sh[a]) * inv_sq;
    }
}

// ---------------- K3: main fused scores kernel ----------------------------
__global__ __launch_bounds__(256) void k_scores(
        const float* __restrict__ ht, const float* __restrict__ W1,
        const float* __restrict__ vhk, const float* __restrict__ kb,
        const float* __restrict__ bg, const float* __restrict__ bbias,
        const float* __restrict__ bm, const float* __restrict__ bv,
        const float* __restrict__ qb) {
    int bn = blockIdx.y;
    int b = bn >> 3, n = bn & 7;
    int t0 = blockIdx.x * TTILE;
    int tid = threadIdx.x;

    __shared__ float xs[TTILE][DD];
    __shared__ float hk[TTILE][QQ + 1];
    __shared__ float lamk[TTILE];
    __shared__ float hck_s[QQ];
    __shared__ float vhk_s[QQ];

    // load input tile + per-head vectors
    for (int i = tid; i < TTILE * DD; i += 256) {
        int t = i / DD, d = i % DD;
        xs[t][d] = ht[((size_t)(b * TT + t0 + t)) * CC + n * DD + d];
    }
    hck_s[tid] = g_hck[(size_t)bn * QQ + tid];
    vhk_s[tid] = vhk[n * QQ + tid];
    __syncthreads();

    // GEMM1: hk[t][q] = sum_d xs[t][d] * W1[n,d,q]    (tid == q)
    float acc[TTILE];
#pragma unroll
    for (int t = 0; t < TTILE; t++) acc[t] = 0.f;
    {
        const float* w = W1 + (size_t)n * DD * QQ + tid;
        for (int d = 0; d < DD; d++) {
            float wv = w[(size_t)d * QQ];
#pragma unroll
            for (int t = 0; t < TTILE; t++) acc[t] += xs[t][d] * wv;
        }
    }
#pragma unroll
    for (int t = 0; t < TTILE; t++) hk[t][tid] = acc[t];
    __syncthreads();

    // lambda_k per t: warp w handles t = 2w, 2w+1
    {
        int w = tid >> 5, lane = tid & 31;
        float ckd = g_ckdot[bn];
        for (int t = w * 2; t < w * 2 + 2; t++) {
            float s = 0.f;
            for (int q = lane; q < QQ; q += 32) s += hk[t][q] * vhk_s[q];
            for (int o = 16; o > 0; o >>= 1) s += __shfl_down_sync(0xffffffffu, s, o);
            if (lane == 0) lamk[t] = 1.f / (1.f + expf(-(s + ckd)));
        }
    }
    __syncthreads();

    // gate + bias + relu + BN + tanh in place (tid == q)
    {
        float hckv = hck_s[tid];
        float kbv = kb[n * QQ + tid];
        float g = bg[tid], bo = bbias[tid], mm = bm[tid];
        float rs = rsqrtf(bv[tid] + 1e-5f);
#pragma unroll
        for (int t = 0; t < TTILE; t++) {
            float lk = lamk[t];
            float m = (1.f - lk) * hk[t][tid] + lk * hckv + kbv;
            float r = fmaxf(m, 0.f);
            hk[t][tid] = tanhf(g * (r - mm) * rs + bo);
        }
    }
    __syncthreads();

    // GEMM2: scores[t][a] = qb[a] + sum_q k2[t][q] * hcq[q][a]   (tid == a)
    if (tid < AA) {
        float s[TTILE];
        float qbv = qb[n * AA + tid];
#pragma unroll
        for (int t = 0; t < TTILE; t++) s[t] = qbv;
        const float* hc = g_hcq + (size_t)bn * QQ * AA + tid;
        for (int q = 0; q < QQ; q++) {
            float w = hc[(size_t)q * AA];
#pragma unroll
            for (int t = 0; t < TTILE; t++) s[t] += hk[t][q] * w;
        }
#pragma unroll
        for (int t = 0; t < TTILE; t++)
            g_scores[(((size_t)b * TT + t0 + t) * NH + n) * AA + tid] = s[t];
    }
}

// ---------------- K4: softmax over T + weighted mean/std pooling ----------
__global__ void k_pool(const float* __restrict__ ht, float* __restrict__ out) {
    int bn = blockIdx.x;
    int b = bn >> 3, n = bn & 7;
    int a = threadIdx.x;
    int chunk = threadIdx.y;
    const int CH = TT / 4;  // 500
    int ts = chunk * CH, te = ts + CH;

    float m = -1e30f, Z = 0.f, S1 = 0.f, S2 = 0.f;
    const float* sc = g_scores + ((size_t)b * TT * NH + n) * AA + a;
    const float* vp = ht + (size_t)b * TT * CC + n * DD + a;
    for (int t = ts; t < te; t++) {
        float s = sc[(size_t)t * NH * AA];
        float v = vp[(size_t)t * CC];
        float nm = fmaxf(m, s);
        float cc = expf(m - nm);
        float w = expf(s - nm);
        Z = Z * cc + w;
        S1 = S1 * cc + w * v;
        S2 = S2 * cc + w * v * v;
        m = nm;
    }
    __shared__ float shm[4][AA], shZ[4][AA], sh1[4][AA], sh2[4][AA];
    shm[chunk][a] = m; shZ[chunk][a] = Z; sh1[chunk][a] = S1; sh2[chunk][a] = S2;
    __syncthreads();
    if (chunk == 0) {
        float M = shm[0][a];
        for (int j = 1; j < 4; j++) M = fmaxf(M, shm[j][a]);
        float Zt = 0.f, S1t = 0.f, S2t = 0.f;
        for (int j = 0; j < 4; j++) {
            float c = expf(shm[j][a] - M);
            Zt += shZ[j][a] * c; S1t += sh1[j][a] * c; S2t += sh2[j][a] * c;
        }
        float mu = S1t / Zt;
        float ex2 = S2t / Zt;
        float rh = sqrtf(fmaxf(ex2 - mu * mu, 1e-9f));
        out[(size_t)b * (2 * CC) + n * DD + a] = mu;
        out[(size_t)b * (2 * CC) + CC + n * DD + a] = rh;
    }
}

// ---------------- launcher ------------------------------------------------
extern "C" void kernel_launch(void* const* d_in, const int* in_sizes, int n_in,
                              void* d_out, int out_size) {
    const float* ht       = (const float*)d_in[0];
    const float* k_proj_W = (const float*)d_in[1];
    const float* query    = (const float*)d_in[2];
    const float* uk_W     = (const float*)d_in[3];
    const float* u_q1W    = (const float*)d_in[4];
    const float* u_q2     = (const float*)d_in[5];
    const float* vhq      = (const float*)d_in[6];
    const float* vhk      = (const float*)d_in[7];
    const float* vcq      = (const float*)d_in[8];
    const float* vck      = (const float*)d_in[9];
    const float* k_proj_b = (const float*)d_in[10];
    const float* q_b      = (const float*)d_in[11];
    const float* u_q1b    = (const float*)d_in[12];
    const float* bnc_g    = (const float*)d_in[13];
    const float* bnc_b    = (const float*)d_in[14];
    const float* bnc_m    = (const float*)d_in[15];
    const float* bnc_v    = (const float*)d_in[16];
    const float* bnk_g    = (const float*)d_in[17];
    const float* bnk_b    = (const float*)d_in[18];
    const float* bnk_m    = (const float*)d_in[19];
    const float* bnk_v    = (const float*)d_in[20];
    float* out = (float*)d_out;

    dim3 gs(CC / 128, BB);
    dim3 bs(128, 8);
    k_stats<<<gs, bs>>>(ht);

    k_qdot<<<NH, 256>>>(query, vhq);

    k_context<<<BB * NH, 256>>>(uk_W, u_q1W, u_q2, query, vcq, vck, u_q1b,
                                bnc_g, bnc_b, bnc_m, bnc_v);

    dim3 gsc(TT / TTILE, BB * NH);
    k_scores<<<gsc, 256>>>(ht, k_proj_W, vhk, k_proj_b,
                           bnk_g, bnk_b, bnk_m, bnk_v, q_b);

    dim3 bp(AA, 4);
    k_pool<<<BB * NH, bp>>>(ht, out);
}

// round 3
// speedup vs baseline: 1.2093x; 1.2093x over previous
#include <cuda_runtime.h>
#include <cuda_bf16.h>
#include <math.h>

// Problem constants
#define BB 16
#define TT 2000
#define CC 1536
#define NH 8
#define DD 192
#define QQ 256
#define AA 192
#define TTILE 20           // divides TT=2000; 10 f32x2 pairs
#define NP 10              // TTILE/2
#define K2STRIDE 24        // floats per k2 row (16B-aligned, >= TTILE, even)

// ---------------- packed fp32x2 helpers -----------------------------------
__device__ __forceinline__ unsigned long long pack2(float x, float y) {
    unsigned long long r;
    asm("mov.b64 %0, {%1, %2};" : "=l"(r) : "f"(x), "f"(y));
    return r;
}
__device__ __forceinline__ float2 unpack2(unsigned long long v) {
    float2 r;
    asm("mov.b64 {%0, %1}, %2;" : "=f"(r.x), "=f"(r.y) : "l"(v));
    return r;
}
__device__ __forceinline__ void fma2(unsigned long long& d, unsigned long long a,
                                     unsigned long long b) {
    asm("fma.rn.f32x2 %0, %1, %2, %0;" : "+l"(d) : "l"(a), "l"(b));
}
__device__ __forceinline__ unsigned long long mul2(unsigned long long a,
                                                   unsigned long long b) {
    unsigned long long r;
    asm("mul.rn.f32x2 %0, %1, %2;" : "=l"(r) : "l"(a), "l"(b));
    return r;
}
__device__ __forceinline__ float tanha(float x) {
    float r;
    asm("tanh.approx.f32 %0, %1;" : "=f"(r) : "f"(x));
    return r;
}

// ---------------- scratch (device globals: no allocations allowed) --------
__device__ float g_c[BB * CC * 2];                 // interleaved mean/std per (b,ch)
__device__ float g_hck[BB * NH * QQ];              // head_ck
__device__ float g_ckdot[BB * NH];                 // sum_q head_ck*vck
__device__ float g_qdot[NH];                       // sum_{q,a} query*vhq
__device__ float g_hcq[(size_t)BB * NH * QQ * AA]; // head_cq / sqrt(Q)
__device__ float g_scores[(size_t)BB * TT * NH * AA]; // [b][t][n][a]

// ---------------- K1: mean/std over time ----------------------------------
__global__ void k_stats(const float* __restrict__ ht) {
    int b = blockIdx.y;
    int ch = blockIdx.x * 128 + threadIdx.x;
    int ty = threadIdx.y;
    float s = 0.f, s2 = 0.f;
    const float* p = ht + (size_t)b * TT * CC + ch;
    for (int t = ty; t < TT; t += 8) {
        float v = p[(size_t)t * CC];
        s += v; s2 += v * v;
    }
    __shared__ float sh0[8][128];
    __shared__ float sh1[8][128];
    sh0[ty][threadIdx.x] = s;
    sh1[ty][threadIdx.x] = s2;
    __syncthreads();
    if (ty == 0) {
        for (int j = 1; j < 8; j++) { s += sh0[j][threadIdx.x]; s2 += sh1[j][threadIdx.x]; }
        float mean = s * (1.f / TT);
        float var = (s2 - (float)TT * mean * mean) * (1.f / (TT - 1));
        float sd = sqrtf(fmaxf(var, 0.f));
        g_c[((size_t)b * CC + ch) * 2 + 0] = mean;
        g_c[((size_t)b * CC + ch) * 2 + 1] = sd;
    }
}

// ---------------- K0: qdot[n] = sum_{q,a} query[n,q,a]*vhq[n,a,q] ---------
__global__ void k_qdot(const float* __restrict__ query, const float* __restrict__ vhq) {
    int n = blockIdx.x;
    int tid = threadIdx.x;
    float acc = 0.f;
    for (int i = tid; i < AA * QQ; i += 256) {
        int a = i >> 8, q = i & 255;
        acc += query[(n * QQ + q) * AA + a] * vhq[n * AA * QQ + i];
    }
    __shared__ float red[256];
    red[tid] = acc;
    __syncthreads();
    for (int off = 128; off > 0; off >>= 1) {
        if (tid < off) red[tid] += red[tid + off];
        __syncthreads();
    }
    if (tid == 0) g_qdot[n] = red[0];
}

// ---------------- K2: per-(b,n) context computations ----------------------
__global__ void k_context(const float* __restrict__ uk_W, const float* __restrict__ u_q1W,
                          const float* __restrict__ u_q2, const float* __restrict__ query,
                          const float* __restrict__ vcq, const float* __restrict__ vck,
                          const float* __restrict__ u_q1b,
                          const float* __restrict__ bnc_g, const float* __restrict__ bnc_b,
                          const float* __restrict__ bnc_m, const float* __restrict__ bnc_v) {
    int bn = blockIdx.x;
    int b = bn >> 3, n = bn & 7;
    int tid = threadIdx.x;
    __shared__ float c_sh[2 * DD];
    __shared__ float t1_sh[QQ];
    __shared__ float cq2_sh[AA];
    __shared__ float red[256];
    __shared__ float lamq_sh;

    for (int i = tid; i < 2 * DD; i += 256)
        c_sh[i] = g_c[((size_t)b * CC + n * DD) * 2 + i];
    __syncthreads();

    // head_ck and cq1 path (tid == q)
    float hck = 0.f, cq1 = 0.f;
    {
        const float* uk = uk_W + n * (2 * DD) * QQ + tid;
        const float* u1 = u_q1W + n * (2 * DD) * QQ + tid;
        for (int l = 0; l < 2 * DD; l++) {
            float cv = c_sh[l];
            hck += cv * uk[(size_t)l * QQ];
            cq1 += cv * u1[(size_t)l * QQ];
        }
        g_hck[(size_t)bn * QQ + tid] = hck;
        cq1 += u_q1b[n * QQ + tid];
        float r = fmaxf(cq1, 0.f);
        float bnv = bnc_g[tid] * (r - bnc_m[tid]) * rsqrtf(bnc_v[tid] + 1e-5f) + bnc_b[tid];
        t1_sh[tid] = tanhf(bnv);
    }
    __syncthreads();

    if (tid < AA) {
        float a2 = 0.f;
        const float* u2 = u_q2 + (size_t)n * QQ * AA + tid;
        for (int m = 0; m < QQ; m++) a2 += t1_sh[m] * u2[(size_t)m * AA];
        cq2_sh[tid] = a2;
    }
    __syncthreads();

    float acc = 0.f;
    for (int i = tid; i < AA * QQ; i += 256) {
        int a = i >> 8;
        acc += cq2_sh[a] * vcq[(size_t)n * AA * QQ + i];
    }
    red[tid] = acc;
    __syncthreads();
    for (int off = 128; off > 0; off >>= 1) {
        if (tid < off) red[tid] += red[tid + off];
        __syncthreads();
    }
    float vcqdot = red[0];
    __syncthreads();

    red[tid] = hck * vck[n * QQ + tid];
    __syncthreads();
    for (int off = 128; off > 0; off >>= 1) {
        if (tid < off) red[tid] += red[tid + off];
        __syncthreads();
    }
    if (tid == 0) {
        g_ckdot[bn] = red[0];
        lamq_sh = 1.f / (1.f + expf(-(g_qdot[n] + vcqdot)));
    }
    __syncthreads();

    float lq = lamq_sh;
    const float inv_sq = 1.f / 16.f;  // 1/sqrt(Q)
    for (int i = tid; i < QQ * AA; i += 256) {
        int a = i % AA;
        g_hcq[(size_t)bn * QQ * AA + i] =
            ((1.f - lq) * query[(size_t)n * QQ * AA + i] + lq * cq2_sh[a]) * inv_sq;
    }
}

// ---------------- K3: main fused scores kernel (f32x2 + transposed tiles) --
__global__ __launch_bounds__(256) void k_scores(
        const float* __restrict__ ht, const float* __restrict__ W1,
        const float* __restrict__ vhk, const float* __restrict__ kb,
        const float* __restrict__ bg, const float* __restrict__ bbias,
        const float* __restrict__ bm, const float* __restrict__ bv,
        const float* __restrict__ qb) {
    int bn = blockIdx.y;
    int b = bn >> 3, n = bn & 7;
    int t0 = blockIdx.x * TTILE;
    int tid = threadIdx.x;

    __shared__ float xs[DD * TTILE];           // [d][t], row stride 20 (80B aligned)
    __shared__ float k2[QQ * K2STRIDE];        // [q][t], row stride 24; also λ scratch
    __shared__ float part[8 * TTILE];
    __shared__ float lamk_sh[TTILE];

    // load + transpose input tile: xs[d][t]
    {
        const float* src = ht + ((size_t)b * TT + t0) * CC + n * DD;
        for (int i = tid; i < TTILE * DD; i += 256) {
            int t = i / DD, d = i - t * DD;   // consecutive tid -> consecutive d (coalesced)
            xs[d * TTILE + t] = src[(size_t)t * CC + d];
        }
    }
    __syncthreads();

    // GEMM1: acc[pair] over t for this thread's q column (tid == q)
    unsigned long long acc[NP];
#pragma unroll
    for (int j = 0; j < NP; j++) acc[j] = 0ULL;
    {
        const float* wp = W1 + (size_t)n * DD * QQ + tid;
#pragma unroll 4
        for (int d = 0; d < DD; d++) {
            float w = wp[(size_t)d * QQ];
            unsigned long long wd = pack2(w, w);
            const ulonglong2* xr = (const ulonglong2*)(xs + d * TTILE);
#pragma unroll
            for (int j = 0; j < 5; j++) {
                ulonglong2 v = xr[j];
                fma2(acc[2 * j], v.x, wd);
                fma2(acc[2 * j + 1], v.y, wd);
            }
        }
    }

    // lambda_k: block reduction of acc * vhk[q] over q, per t
    {
        float vq = vhk[n * QQ + tid];
        unsigned long long vd = pack2(vq, vq);
        unsigned long long* myred = (unsigned long long*)(k2 + tid * K2STRIDE);
#pragma unroll
        for (int j = 0; j < NP; j++) myred[j] = mul2(acc[j], vd);
    }
    __syncthreads();
    {
        int tt = tid & 31, r = tid >> 5;
        if (tt < TTILE) {
            float s = 0.f;
#pragma unroll 8
            for (int q = r; q < QQ; q += 8) s += k2[q * K2STRIDE + tt];
            part[r * TTILE + tt] = s;
        }
    }
    __syncthreads();
    if (tid < TTILE) {
        float s = 0.f;
#pragma unroll
        for (int r2 = 0; r2 < 8; r2++) s += part[r2 * TTILE + tid];
        float ckd = g_ckdot[bn];
        lamk_sh[tid] = 1.f / (1.f + expf(-(s + ckd)));
    }
    __syncthreads();

    // gate + bias + relu + BN + tanh in registers; write transposed k2[q][t]
    {
        float hckq = g_hck[(size_t)bn * QQ + tid];
        float kbv = kb[n * QQ + tid];
        float grs = bg[tid] * rsqrtf(bv[tid] + 1e-5f);
        float bov = bbias[tid], mmv = bm[tid];
        unsigned long long* krow = (unsigned long long*)(k2 + tid * K2STRIDE);
#pragma unroll
        for (int j = 0; j < NP; j++) {
            float2 x = unpack2(acc[j]);
            float l0 = lamk_sh[2 * j], l1 = lamk_sh[2 * j + 1];
            float m0 = fmaf(l0, hckq - x.x, x.x) + kbv;
            float m1 = fmaf(l1, hckq - x.y, x.y) + kbv;
            m0 = fmaxf(m0, 0.f); m1 = fmaxf(m1, 0.f);
            float a0 = tanha(fmaf(grs, m0 - mmv, bov));
            float a1 = tanha(fmaf(grs, m1 - mmv, bov));
            krow[j] = pack2(a0, a1);
        }
    }
    __syncthreads();

    // GEMM2: scores[t][a] = qb[a] + sum_q k2[q][t] * hcq[q][a]   (tid == a)
    if (tid < AA) {
        float qbv = qb[n * AA + tid];
        unsigned long long s[NP];
        unsigned long long qp = pack2(qbv, qbv);
#pragma unroll
        for (int j = 0; j < NP; j++) s[j] = qp;
        const float* hp = g_hcq + (size_t)bn * QQ * AA + tid;
#pragma unroll 4
        for (int q = 0; q < QQ; q++) {
            float w = hp[(size_t)q * AA];
            unsigned long long wd = pack2(w, w);
            const ulonglong2* kr = (const ulonglong2*)(k2 + q * K2STRIDE);
#pragma unroll
            for (int j = 0; j < 5; j++) {
                ulonglong2 v = kr[j];
                fma2(s[2 * j], v.x, wd);
                fma2(s[2 * j + 1], v.y, wd);
            }
        }
        float* op = g_scores + (((size_t)b * TT + t0) * NH + n) * AA + tid;
#pragma unroll
        for (int j = 0; j < NP; j++) {
            float2 v = unpack2(s[j]);
            op[(size_t)(2 * j) * NH * AA] = v.x;
            op[(size_t)(2 * j + 1) * NH * AA] = v.y;
        }
    }
}

// ---------------- K4: softmax over T + weighted mean/std pooling ----------
__global__ void k_pool(const float* __restrict__ ht, float* __restrict__ out) {
    int bn = blockIdx.x;
    int b = bn >> 3, n = bn & 7;
    int a = threadIdx.x;
    int chunk = threadIdx.y;
    const int CH = TT / 4;  // 500
    int ts = chunk * CH, te = ts + CH;

    float m = -1e30f, Z = 0.f, S1 = 0.f, S2 = 0.f;
    const float* sc = g_scores + ((size_t)b * TT * NH + n) * AA + a;
    const float* vp = ht + (size_t)b * TT * CC + n * DD + a;
    for (int t = ts; t < te; t++) {
        float s = sc[(size_t)t * NH * AA];
        float v = vp[(size_t)t * CC];
        float nm = fmaxf(m, s);
        float cc = expf(m - nm);
        float w = expf(s - nm);
        Z = Z * cc + w;
        S1 = S1 * cc + w * v;
        S2 = S2 * cc + w * v * v;
        m = nm;
    }
    __shared__ float shm[4][AA], shZ[4][AA], sh1[4][AA], sh2[4][AA];
    shm[chunk][a] = m; shZ[chunk][a] = Z; sh1[chunk][a] = S1; sh2[chunk][a] = S2;
    __syncthreads();
    if (chunk == 0) {
        float M = shm[0][a];
        for (int j = 1; j < 4; j++) M = fmaxf(M, shm[j][a]);
        float Zt = 0.f, S1t = 0.f, S2t = 0.f;
        for (int j = 0; j < 4; j++) {
            float c = expf(shm[j][a] - M);
            Zt += shZ[j][a] * c; S1t += sh1[j][a] * c; S2t += sh2[j][a] * c;
        }
        float mu = S1t / Zt;
        float ex2 = S2t / Zt;
        float rh = sqrtf(fmaxf(ex2 - mu * mu, 1e-9f));
        out[(size_t)b * (2 * CC) + n * DD + a] = mu;
        out[(size_t)b * (2 * CC) + CC + n * DD + a] = rh;
    }
}

// ---------------- launcher ------------------------------------------------
extern "C" void kernel_launch(void* const* d_in, const int* in_sizes, int n_in,
                              void* d_out, int out_size) {
    const float* ht       = (const float*)d_in[0];
    const float* k_proj_W = (const float*)d_in[1];
    const float* query    = (const float*)d_in[2];
    const float* uk_W     = (const float*)d_in[3];
    const float* u_q1W    = (const float*)d_in[4];
    const float* u_q2     = (const float*)d_in[5];
    const float* vhq      = (const float*)d_in[6];
    const float* vhk      = (const float*)d_in[7];
    const float* vcq      = (const float*)d_in[8];
    const float* vck      = (const float*)d_in[9];
    const float* k_proj_b = (const float*)d_in[10];
    const float* q_b      = (const float*)d_in[11];
    const float* u_q1b    = (const float*)d_in[12];
    const float* bnc_g    = (const float*)d_in[13];
    const float* bnc_b    = (const float*)d_in[14];
    const float* bnc_m    = (const float*)d_in[15];
    const float* bnc_v    = (const float*)d_in[16];
    const float* bnk_g    = (const float*)d_in[17];
    const float* bnk_b    = (const float*)d_in[18];
    const float* bnk_m    = (const float*)d_in[19];
    const float* bnk_v    = (const float*)d_in[20];
    float* out = (float*)d_out;

    dim3 gs(CC / 128, BB);
    dim3 bs(128, 8);
    k_stats<<<gs, bs>>>(ht);

    k_qdot<<<NH, 256>>>(query, vhq);

    k_context<<<BB * NH, 256>>>(uk_W, u_q1W, u_q2, query, vcq, vck, u_q1b,
                                bnc_g, bnc_b, bnc_m, bnc_v);

    dim3 gsc(TT / TTILE, BB * NH);
    k_scores<<<gsc, 256>>>(ht, k_proj_W, vhk, k_proj_b,
                           bnk_g, bnk_b, bnk_m, bnk_v, q_b);

    dim3 bp(AA, 4);
    k_pool<<<BB * NH, bp>>>(ht, out);
}

// round 5
// speedup vs baseline: 3.1045x; 2.5672x over previous
#include <cuda_runtime.h>
#include <cuda_bf16.h>
#include <math.h>
#include <stdint.h>

// Problem constants
#define BB 16
#define TT 2000
#define CC 1536
#define NH 8
#define DD 192
#define QQ 256
#define AA 192

// ===================== warp-MMA helpers (sm_80+ baseline, no 'a' gate) =====
__device__ __forceinline__ uint32_t smem_u32(const void* p) {
    uint32_t a;
    asm("{ .reg .u64 t; cvta.to.shared.u64 t, %1; cvt.u32.u64 %0, t; }"
        : "=r"(a) : "l"(p));
    return a;
}
__device__ __forceinline__ void ldsm_x4(uint32_t r[4], uint32_t addr) {
    asm volatile("ldmatrix.sync.aligned.m8n8.x4.shared.b16 {%0,%1,%2,%3}, [%4];"
                 : "=r"(r[0]), "=r"(r[1]), "=r"(r[2]), "=r"(r[3]) : "r"(addr));
}
__device__ __forceinline__ void mma_bf16(float c[4], const uint32_t a[4],
                                         uint32_t b0, uint32_t b1) {
    asm volatile("mma.sync.aligned.m16n8k16.row.col.f32.bf16.bf16.f32 "
                 "{%0,%1,%2,%3}, {%4,%5,%6,%7}, {%8,%9}, {%0,%1,%2,%3};"
                 : "+f"(c[0]), "+f"(c[1]), "+f"(c[2]), "+f"(c[3])
                 : "r"(a[0]), "r"(a[1]), "r"(a[2]), "r"(a[3]), "r"(b0), "r"(b1));
}
__device__ __forceinline__ uint32_t pack_bf(float lo, float hi) {
    uint32_t r;
    asm("cvt.rn.bf16x2.f32 %0, %1, %2;" : "=r"(r) : "f"(hi), "f"(lo));
    return r;
}
__device__ __forceinline__ float bflo(uint32_t u) { return __uint_as_float(u << 16); }
__device__ __forceinline__ float bfhi(uint32_t u) { return __uint_as_float(u & 0xffff0000u); }
__device__ __forceinline__ float tanha(float x) {
    float r; asm("tanh.approx.f32 %0, %1;" : "=f"(r) : "f"(x)); return r;
}

// ---------------- scratch (device globals: no allocations allowed) --------
__device__ float g_c[BB * CC * 2];
__device__ float g_hck[BB * NH * QQ];
__device__ float g_ckdot[BB * NH];
__device__ float g_qdot[NH];
__device__ __nv_bfloat16 g_w1t[NH * QQ * DD];                 // W1^T [n][q][d] bf16
__device__ __nv_bfloat16 g_hcqT[(size_t)BB * NH * AA * QQ];   // hcq^T/sqrt(Q) [bn][a][q]
__device__ float g_scores[(size_t)BB * TT * NH * AA];         // [b][t][n][a]

// ---------------- K1: mean/std over time ----------------------------------
__global__ void k_stats(const float* __restrict__ ht) {
    int b = blockIdx.y;
    int ch = blockIdx.x * 128 + threadIdx.x;
    int ty = threadIdx.y;
    float s = 0.f, s2 = 0.f;
    const float* p = ht + (size_t)b * TT * CC + ch;
    for (int t = ty; t < TT; t += 8) {
        float v = p[(size_t)t * CC];
        s += v; s2 += v * v;
    }
    __shared__ float sh0[8][128];
    __shared__ float sh1[8][128];
    sh0[ty][threadIdx.x] = s;
    sh1[ty][threadIdx.x] = s2;
    __syncthreads();
    if (ty == 0) {
        for (int j = 1; j < 8; j++) { s += sh0[j][threadIdx.x]; s2 += sh1[j][threadIdx.x]; }
        float mean = s * (1.f / TT);
        float var = (s2 - (float)TT * mean * mean) * (1.f / (TT - 1));
        float sd = sqrtf(fmaxf(var, 0.f));
        g_c[((size_t)b * CC + ch) * 2 + 0] = mean;
        g_c[((size_t)b * CC + ch) * 2 + 1] = sd;
    }
}

// ---------------- K0: qdot[n] ----------------------------------------------
__global__ void k_qdot(const float* __restrict__ query, const float* __restrict__ vhq) {
    int n = blockIdx.x;
    int tid = threadIdx.x;
    float acc = 0.f;
    for (int i = tid; i < AA * QQ; i += 256) {
        int a = i >> 8, q = i & 255;
        acc += query[(n * QQ + q) * AA + a] * vhq[n * AA * QQ + i];
    }
    __shared__ float red[256];
    red[tid] = acc;
    __syncthreads();
    for (int off = 128; off > 0; off >>= 1) {
        if (tid < off) red[tid] += red[tid + off];
        __syncthreads();
    }
    if (tid == 0) g_qdot[n] = red[0];
}

// ---------------- K-prep: W1^T -> bf16 ------------------------------------
__global__ void k_prepw(const float* __restrict__ W1) {
    int n = blockIdx.x;
    for (int i = threadIdx.x; i < QQ * DD; i += 256) {
        int q = i / DD, d = i - q * DD;
        g_w1t[(size_t)n * QQ * DD + i] = __float2bfloat16_rn(W1[((size_t)n * DD + d) * QQ + q]);
    }
}

// ---------------- K2: per-(b,n) context ------------------------------------
__global__ void k_context(const float* __restrict__ uk_W, const float* __restrict__ u_q1W,
                          const float* __restrict__ u_q2, const float* __restrict__ query,
                          const float* __restrict__ vcq, const float* __restrict__ vck,
                          const float* __restrict__ u_q1b,
                          const float* __restrict__ bnc_g, const float* __restrict__ bnc_b,
                          const float* __restrict__ bnc_m, const float* __restrict__ bnc_v) {
    int bn = blockIdx.x;
    int b = bn >> 3, n = bn & 7;
    int tid = threadIdx.x;
    __shared__ float c_sh[2 * DD];
    __shared__ float t1_sh[QQ];
    __shared__ float cq2_sh[AA];
    __shared__ float red[256];
    __shared__ float lamq_sh;

    for (int i = tid; i < 2 * DD; i += 256)
        c_sh[i] = g_c[((size_t)b * CC + n * DD) * 2 + i];
    __syncthreads();

    float hck = 0.f, cq1 = 0.f;
    {
        const float* uk = uk_W + n * (2 * DD) * QQ + tid;
        const float* u1 = u_q1W + n * (2 * DD) * QQ + tid;
        for (int l = 0; l < 2 * DD; l++) {
            float cv = c_sh[l];
            hck += cv * uk[(size_t)l * QQ];
            cq1 += cv * u1[(size_t)l * QQ];
        }
        g_hck[(size_t)bn * QQ + tid] = hck;
        cq1 += u_q1b[n * QQ + tid];
        float r = fmaxf(cq1, 0.f);
        float bnv = bnc_g[tid] * (r - bnc_m[tid]) * rsqrtf(bnc_v[tid] + 1e-5f) + bnc_b[tid];
        t1_sh[tid] = tanhf(bnv);
    }
    __syncthreads();

    if (tid < AA) {
        float a2 = 0.f;
        const float* u2 = u_q2 + (size_t)n * QQ * AA + tid;
        for (int m = 0; m < QQ; m++) a2 += t1_sh[m] * u2[(size_t)m * AA];
        cq2_sh[tid] = a2;
    }
    __syncthreads();

    float acc = 0.f;
    for (int i = tid; i < AA * QQ; i += 256) {
        int a = i >> 8;
        acc += cq2_sh[a] * vcq[(size_t)n * AA * QQ + i];
    }
    red[tid] = acc;
    __syncthreads();
    for (int off = 128; off > 0; off >>= 1) {
        if (tid < off) red[tid] += red[tid + off];
        __syncthreads();
    }
    float vcqdot = red[0];
    __syncthreads();

    red[tid] = hck * vck[n * QQ + tid];
    __syncthreads();
    for (int off = 128; off > 0; off >>= 1) {
        if (tid < off) red[tid] += red[tid + off];
        __syncthreads();
    }
    if (tid == 0) {
        g_ckdot[bn] = red[0];
        lamq_sh = 1.f / (1.f + expf(-(g_qdot[n] + vcqdot)));
    }
    __syncthreads();

    float lq = lamq_sh;
    const float inv_sq = 1.f / 16.f;  // 1/sqrt(Q)
    for (int i = tid; i < QQ * AA; i += 256) {
        int q = i / AA, a = i - q * AA;
        float v = ((1.f - lq) * query[(size_t)n * QQ * AA + i] + lq * cq2_sh[a]) * inv_sq;
        g_hcqT[(size_t)bn * AA * QQ + (size_t)a * QQ + q] = __float2bfloat16_rn(v);
    }
}

// ---------------- K3: warp-MMA fused scores kernel -------------------------
// smem (dynamic, byte offsets):
//  SM_XS  [0, 51200):       x tile bf16 [128][200]; reused for hcq chunk [96][264]
//  SM_HK  [51200, 118784):  hk / k2 bf16 [128][264]
//  SM_W1  [118784, 144384): W1 chunk bf16 [64][200]
//  SM_AUX [144384, ...):    per-q/per-a fp32 arrays + lambda
#define XS_STRIDE 200
#define HK_STRIDE 264
#define SM_XS 0
#define SM_HK 51200
#define SM_W1 118784
#define SM_AUX 144384
#define AXH_HCK  (SM_AUX + 0)
#define AXH_KBV  (SM_AUX + 1024)
#define AXH_GRS  (SM_AUX + 2048)
#define AXH_BETA (SM_AUX + 3072)
#define AXH_VHK  (SM_AUX + 4096)
#define AXH_QB   (SM_AUX + 5120)
#define AXH_LAM  (SM_AUX + 6144)
#define SMEM_SC  (SM_AUX + 6656)

__global__ __launch_bounds__(256) void k_scores_mma(
        const float* __restrict__ ht, const float* __restrict__ kb,
        const float* __restrict__ bg, const float* __restrict__ bbias,
        const float* __restrict__ bm, const float* __restrict__ bv,
        const float* __restrict__ vhk, const float* __restrict__ qb) {
    extern __shared__ char smem[];
    uint32_t sb = smem_u32(smem);
    int tid = threadIdx.x;
    int w = tid >> 5, lane = tid & 31;
    int bn = blockIdx.y;
    int b = bn >> 3, n = bn & 7;
    int t0 = blockIdx.x * 128;

    // aux constant arrays
    {
        int i = tid;  // 256 threads == QQ
        float g = bg[i];
        float grs = g * rsqrtf(bv[i] + 1e-5f);
        ((float*)(smem + AXH_GRS))[i] = grs;
        ((float*)(smem + AXH_BETA))[i] = bbias[i] - grs * bm[i];
        ((float*)(smem + AXH_HCK))[i] = g_hck[(size_t)bn * QQ + i];
        ((float*)(smem + AXH_KBV))[i] = kb[n * QQ + i];
        ((float*)(smem + AXH_VHK))[i] = vhk[n * QQ + i];
        if (i < AA) ((float*)(smem + AXH_QB))[i] = qb[n * AA + i];
    }

    // ---- load x tile (fp32 -> bf16), rows padded with zeros past TT ----
    {
        const float* xb = ht + ((size_t)b * TT + t0) * CC + n * DD;
        for (int it = 0; it < 24; it++) {
            int idx = it * 256 + tid;            // 128 rows x 48 float4
            int row = idx / 48, c4 = idx - row * 48;
            float4 v = make_float4(0.f, 0.f, 0.f, 0.f);
            if (t0 + row < TT) v = *(const float4*)(xb + (size_t)row * CC + c4 * 4);
            uint2 pk = make_uint2(pack_bf(v.x, v.y), pack_bf(v.z, v.w));
            *(uint2*)(smem + SM_XS + (row * XS_STRIDE + c4 * 4) * 2) = pk;
        }
    }

    // fragment base addresses (A from xs, B from w1 chunk)
    uint32_t abase = sb + SM_XS + ((w * 16 + (lane & 15)) * XS_STRIDE + (lane >> 4) * 8) * 2;
    uint32_t bbase = sb + SM_W1 + (((lane >> 4) * 8 + (lane & 7)) * XS_STRIDE + ((lane >> 3) & 1) * 8) * 2;

    // ---- GEMM1 over 4 q-chunks of 64; lambda partials in-register ----
    float lam0 = 0.f, lam1 = 0.f;
    for (int qc = 0; qc < 4; qc++) {
        __syncthreads();   // xs ready (qc=0) / prev chunk consumers done
        {
            const uint4* wsrc = (const uint4*)(g_w1t + ((size_t)n * QQ + qc * 64) * DD);
            for (int it = 0; it < 6; it++) {
                int idx = it * 256 + tid;        // 64 rows x 24 uint4
                int row = idx / 24, c8 = idx - row * 24;
                *(uint4*)(smem + SM_W1 + (row * XS_STRIDE + c8 * 8) * 2) = wsrc[idx];
            }
        }
        __syncthreads();

        float c[4][2][4];
#pragma unroll
        for (int p = 0; p < 4; p++)
#pragma unroll
            for (int j = 0; j < 2; j++)
#pragma unroll
                for (int e = 0; e < 4; e++) c[p][j][e] = 0.f;

        for (int kk = 0; kk < 12; kk++) {
            uint32_t a[4];
            ldsm_x4(a, abase + kk * 32);
#pragma unroll
            for (int p = 0; p < 4; p++) {
                uint32_t bf[4];
                ldsm_x4(bf, bbase + p * 16 * XS_STRIDE * 2 + kk * 32);
                mma_bf16(c[p][0], a, bf[0], bf[1]);
                mma_bf16(c[p][1], a, bf[2], bf[3]);
            }
        }

        // lambda partial + store hk bf16
        const float* vhk_s = (const float*)(smem + AXH_VHK);
        int r0 = w * 16 + (lane >> 2);
#pragma unroll
        for (int p = 0; p < 4; p++) {
#pragma unroll
            for (int j = 0; j < 2; j++) {
                int col = qc * 64 + p * 16 + j * 8 + 2 * (lane & 3);
                float v0 = vhk_s[col], v1 = vhk_s[col + 1];
                lam0 += c[p][j][0] * v0 + c[p][j][1] * v1;
                lam1 += c[p][j][2] * v0 + c[p][j][3] * v1;
                *(uint32_t*)(smem + SM_HK + (r0 * HK_STRIDE + col) * 2) =
                    pack_bf(c[p][j][0], c[p][j][1]);
                *(uint32_t*)(smem + SM_HK + ((r0 + 8) * HK_STRIDE + col) * 2) =
                    pack_bf(c[p][j][2], c[p][j][3]);
            }
        }
    }

    // finalize lambda (reduce across the 4 lanes sharing each row)
    lam0 += __shfl_xor_sync(0xffffffffu, lam0, 1);
    lam0 += __shfl_xor_sync(0xffffffffu, lam0, 2);
    lam1 += __shfl_xor_sync(0xffffffffu, lam1, 1);
    lam1 += __shfl_xor_sync(0xffffffffu, lam1, 2);
    {
        float ckd = g_ckdot[bn];
        if ((lane & 3) == 0) {
            float* lam_sh = (float*)(smem + AXH_LAM);
            lam_sh[w * 16 + (lane >> 2)] = 1.f / (1.f + expf(-(lam0 + ckd)));
            lam_sh[w * 16 + (lane >> 2) + 8] = 1.f / (1.f + expf(-(lam1 + ckd)));
        }
    }
    __syncthreads();

    // ---- activation in place: k2 = tanh(grs*relu(gate + kb) + beta) ----
    {
        int row = w * 16 + (lane >> 1);
        int cb = (lane & 1) * 128;
        float lam = ((const float*)(smem + AXH_LAM))[row];
        const float* hck_s = (const float*)(smem + AXH_HCK);
        const float* kbv_s = (const float*)(smem + AXH_KBV);
        const float* grs_s = (const float*)(smem + AXH_GRS);
        const float* bet_s = (const float*)(smem + AXH_BETA);
        uint32_t* hp = (uint32_t*)(smem + SM_HK + (row * HK_STRIDE + cb) * 2);
        for (int j = 0; j < 16; j++) {
            uint4 v = *(uint4*)(hp + j * 4);
            uint32_t* vr = (uint32_t*)&v;
#pragma unroll
            for (int e = 0; e < 4; e++) {
                int c0 = cb + j * 8 + 2 * e;
                float h0 = bflo(vr[e]), h1 = bfhi(vr[e]);
                float m0 = fmaf(lam, hck_s[c0] - h0, h0) + kbv_s[c0];
                float m1 = fmaf(lam, hck_s[c0 + 1] - h1, h1) + kbv_s[c0 + 1];
                m0 = fmaxf(m0, 0.f); m1 = fmaxf(m1, 0.f);
                float a0 = tanha(fmaf(grs_s[c0], m0, bet_s[c0]));
                float a1 = tanha(fmaf(grs_s[c0 + 1], m1, bet_s[c0 + 1]));
                vr[e] = pack_bf(a0, a1);
            }
            *(uint4*)(hp + j * 4) = v;
        }
    }

    // ---- GEMM2 over 2 a-chunks of 96 (hcq chunk staged in xs region) ----
    uint32_t abase2 = sb + SM_HK + ((w * 16 + (lane & 15)) * HK_STRIDE + (lane >> 4) * 8) * 2;
    uint32_t bbase2 = sb + SM_XS + (((lane >> 4) * 8 + (lane & 7)) * HK_STRIDE + ((lane >> 3) & 1) * 8) * 2;
    int r0 = w * 16 + (lane >> 2);
    int t_a = t0 + r0, t_b = t0 + r0 + 8;
    const float* qb_s = (const float*)(smem + AXH_QB);

    for (int ac = 0; ac < 2; ac++) {
        __syncthreads();   // activation done (ac=0) / prev chunk consumers done
        {
            const uint4* hs = (const uint4*)(g_hcqT + ((size_t)bn * AA + ac * 96) * QQ);
            for (int it = 0; it < 12; it++) {
                int idx = it * 256 + tid;        // 96 rows x 32 uint4
                int row = idx / 32, c8 = idx - row * 32;
                *(uint4*)(smem + SM_XS + (row * HK_STRIDE + c8 * 8) * 2) = hs[idx];
            }
        }
        __syncthreads();

        float c2[6][2][4];
#pragma unroll
        for (int p = 0; p < 6; p++)
#pragma unroll
            for (int j = 0; j < 2; j++)
#pragma unroll
                for (int e = 0; e < 4; e++) c2[p][j][e] = 0.f;

        for (int kk = 0; kk < 16; kk++) {
            uint32_t a[4];
            ldsm_x4(a, abase2 + kk * 32);
#pragma unroll
            for (int p = 0; p < 6; p++) {
                uint32_t bf[4];
                ldsm_x4(bf, bbase2 + p * 16 * HK_STRIDE * 2 + kk * 32);
                mma_bf16(c2[p][0], a, bf[0], bf[1]);
                mma_bf16(c2[p][1], a, bf[2], bf[3]);
            }
        }

        // epilogue: + q_b, guarded stores
#pragma unroll
        for (int p = 0; p < 6; p++) {
#pragma unroll
            for (int j = 0; j < 2; j++) {
                int col = ac * 96 + p * 16 + j * 8 + 2 * (lane & 3);
                float q0 = qb_s[col], q1 = qb_s[col + 1];
                if (t_a < TT) {
                    float2 v = make_float2(c2[p][j][0] + q0, c2[p][j][1] + q1);
                    *(float2*)(g_scores + (((size_t)b * TT + t_a) * NH + n) * AA + col) = v;
                }
                if (t_b < TT) {
                    float2 v = make_float2(c2[p][j][2] + q0, c2[p][j][3] + q1);
                    *(float2*)(g_scores + (((size_t)b * TT + t_b) * NH + n) * AA + col) = v;
                }
            }
        }
    }
}

// ---------------- K4: softmax over T + weighted mean/std pooling ----------
__global__ void k_pool(const float* __restrict__ ht, float* __restrict__ out) {
    int bn = blockIdx.x;
    int b = bn >> 3, n = bn & 7;
    int a = threadIdx.x;
    int chunk = threadIdx.y;
    const int CH = TT / 4;  // 500
    int ts = chunk * CH, te = ts + CH;

    float m = -1e30f, Z = 0.f, S1 = 0.f, S2 = 0.f;
    const float* sc = g_scores + ((size_t)b * TT * NH + n) * AA + a;
    const float* vp = ht + (size_t)b * TT * CC + n * DD + a;
    for (int t = ts; t < te; t++) {
        float s = sc[(size_t)t * NH * AA];
        float v = vp[(size_t)t * CC];
        float nm = fmaxf(m, s);
        float cc = expf(m - nm);
        float w = expf(s - nm);
        Z = Z * cc + w;
        S1 = S1 * cc + w * v;
        S2 = S2 * cc + w * v * v;
        m = nm;
    }
    __shared__ float shm[4][AA], shZ[4][AA], sh1[4][AA], sh2[4][AA];
    shm[chunk][a] = m; shZ[chunk][a] = Z; sh1[chunk][a] = S1; sh2[chunk][a] = S2;
    __syncthreads();
    if (chunk == 0) {
        float M = shm[0][a];
        for (int j = 1; j < 4; j++) M = fmaxf(M, shm[j][a]);
        float Zt = 0.f, S1t = 0.f, S2t = 0.f;
        for (int j = 0; j < 4; j++) {
            float c = expf(shm[j][a] - M);
            Zt += shZ[j][a] * c; S1t += sh1[j][a] * c; S2t += sh2[j][a] * c;
        }
        float mu = S1t / Zt;
        float ex2 = S2t / Zt;
        float rh = sqrtf(fmaxf(ex2 - mu * mu, 1e-9f));
        out[(size_t)b * (2 * CC) + n * DD + a] = mu;
        out[(size_t)b * (2 * CC) + CC + n * DD + a] = rh;
    }
}

// ---------------- launcher ------------------------------------------------
extern "C" void kernel_launch(void* const* d_in, const int* in_sizes, int n_in,
                              void* d_out, int out_size) {
    const float* ht       = (const float*)d_in[0];
    const float* k_proj_W = (const float*)d_in[1];
    const float* query    = (const float*)d_in[2];
    const float* uk_W     = (const float*)d_in[3];
    const float* u_q1W    = (const float*)d_in[4];
    const float* u_q2     = (const float*)d_in[5];
    const float* vhq      = (const float*)d_in[6];
    const float* vhk      = (const float*)d_in[7];
    const float* vcq      = (const float*)d_in[8];
    const float* vck      = (const float*)d_in[9];
    const float* k_proj_b = (const float*)d_in[10];
    const float* q_b      = (const float*)d_in[11];
    const float* u_q1b    = (const float*)d_in[12];
    const float* bnc_g    = (const float*)d_in[13];
    const float* bnc_b    = (const float*)d_in[14];
    const float* bnc_m    = (const float*)d_in[15];
    const float* bnc_v    = (const float*)d_in[16];
    const float* bnk_g    = (const float*)d_in[17];
    const float* bnk_b    = (const float*)d_in[18];
    const float* bnk_m    = (const float*)d_in[19];
    const float* bnk_v    = (const float*)d_in[20];
    float* out = (float*)d_out;

    static int smem_set = 0;
    if (!smem_set) {
        cudaFuncSetAttribute(k_scores_mma,
                             cudaFuncAttributeMaxDynamicSharedMemorySize, SMEM_SC);
        smem_set = 1;
    }

    dim3 gs(CC / 128, BB);
    dim3 bs(128, 8);
    k_stats<<<gs, bs>>>(ht);

    k_qdot<<<NH, 256>>>(query, vhq);
    k_prepw<<<NH, 256>>>(k_proj_W);

    k_context<<<BB * NH, 256>>>(uk_W, u_q1W, u_q2, query, vcq, vck, u_q1b,
                                bnc_g, bnc_b, bnc_m, bnc_v);

    dim3 gsc(16, BB * NH);   // 16 t-tiles of 128 (last padded) x 128 (b,n)
    k_scores_mma<<<gsc, 256, SMEM_SC>>>(ht, k_proj_b, bnk_g, bnk_b, bnk_m, bnk_v,
                                        vhk, q_b);

    dim3 bp(AA, 4);
    k_pool<<<BB * NH, bp>>>(ht, out);
}

// round 6
// speedup vs baseline: 3.5152x; 1.1323x over previous
#include <cuda_runtime.h>
#include <cuda_bf16.h>
#include <math.h>
#include <stdint.h>

// Problem constants
#define BB 16
#define TT 2000
#define CC 1536
#define NH 8
#define DD 192
#define QQ 256
#define AA 192

// ===================== warp-MMA helpers (sm_80+ baseline, no 'a' gate) =====
__device__ __forceinline__ uint32_t smem_u32(const void* p) {
    uint32_t a;
    asm("{ .reg .u64 t; cvta.to.shared.u64 t, %1; cvt.u32.u64 %0, t; }"
        : "=r"(a) : "l"(p));
    return a;
}
__device__ __forceinline__ void ldsm_x4(uint32_t r[4], uint32_t addr) {
    asm volatile("ldmatrix.sync.aligned.m8n8.x4.shared.b16 {%0,%1,%2,%3}, [%4];"
                 : "=r"(r[0]), "=r"(r[1]), "=r"(r[2]), "=r"(r[3]) : "r"(addr));
}
__device__ __forceinline__ void mma_bf16(float c[4], const uint32_t a[4],
                                         uint32_t b0, uint32_t b1) {
    asm volatile("mma.sync.aligned.m16n8k16.row.col.f32.bf16.bf16.f32 "
                 "{%0,%1,%2,%3}, {%4,%5,%6,%7}, {%8,%9}, {%0,%1,%2,%3};"
                 : "+f"(c[0]), "+f"(c[1]), "+f"(c[2]), "+f"(c[3])
                 : "r"(a[0]), "r"(a[1]), "r"(a[2]), "r"(a[3]), "r"(b0), "r"(b1));
}
__device__ __forceinline__ uint32_t pack_bf(float lo, float hi) {
    uint32_t r;
    asm("cvt.rn.bf16x2.f32 %0, %1, %2;" : "=r"(r) : "f"(hi), "f"(lo));
    return r;
}
__device__ __forceinline__ float bflo(uint32_t u) { return __uint_as_float(u << 16); }
__device__ __forceinline__ float bfhi(uint32_t u) { return __uint_as_float(u & 0xffff0000u); }
__device__ __forceinline__ float tanha(float x) {
    float r; asm("tanh.approx.f32 %0, %1;" : "=f"(r) : "f"(x)); return r;
}

// ---------------- scratch (device globals: no allocations allowed) --------
__device__ float g_c[BB * CC * 2];
__device__ float g_hck[BB * NH * QQ];
__device__ float g_t1[BB * NH * QQ];
__device__ float g_cq2[BB * NH * AA];
__device__ float g_vcqsum[NH * AA];
__device__ float g_ckdot[BB * NH];
__device__ float g_qdot[NH];
__device__ float g_qT[NH * AA * QQ];                          // query^T [n][a][q]
__device__ __nv_bfloat16 g_w1t[NH * QQ * DD];                 // W1^T [n][q][d] bf16
__device__ __nv_bfloat16 g_hcqT[(size_t)BB * NH * AA * QQ];   // hcq^T/sqrt(Q) [bn][a][q]
__device__ float g_scores[(size_t)BB * TT * NH * AA];         // [b][t][n][a]

// ---------------- K1: mean/std over time ----------------------------------
__global__ void k_stats(const float* __restrict__ ht) {
    int b = blockIdx.y;
    int ch = blockIdx.x * 128 + threadIdx.x;
    int ty = threadIdx.y;
    float s = 0.f, s2 = 0.f;
    const float* p = ht + (size_t)b * TT * CC + ch;
    for (int t = ty; t < TT; t += 8) {
        float v = p[(size_t)t * CC];
        s += v; s2 += v * v;
    }
    __shared__ float sh0[8][128];
    __shared__ float sh1[8][128];
    sh0[ty][threadIdx.x] = s;
    sh1[ty][threadIdx.x] = s2;
    __syncthreads();
    if (ty == 0) {
        for (int j = 1; j < 8; j++) { s += sh0[j][threadIdx.x]; s2 += sh1[j][threadIdx.x]; }
        float mean = s * (1.f / TT);
        float var = (s2 - (float)TT * mean * mean) * (1.f / (TT - 1));
        float sd = sqrtf(fmaxf(var, 0.f));
        g_c[((size_t)b * CC + ch) * 2 + 0] = mean;
        g_c[((size_t)b * CC + ch) * 2 + 1] = sd;
    }
}

// ---------------- K0: qdot[n] + vcq_sum[n][a] ------------------------------
__global__ void k_qdot(const float* __restrict__ query, const float* __restrict__ vhq,
                       const float* __restrict__ vcq) {
    int n = blockIdx.x;
    int tid = threadIdx.x;
    float acc = 0.f;
    for (int i = tid; i < AA * QQ; i += 256) {
        int a = i >> 8, q = i & 255;
        acc += query[(n * QQ + q) * AA + a] * vhq[n * AA * QQ + i];
    }
    __shared__ float red[256];
    red[tid] = acc;
    __syncthreads();
    for (int off = 128; off > 0; off >>= 1) {
        if (tid < off) red[tid] += red[tid + off];
        __syncthreads();
    }
    if (tid == 0) g_qdot[n] = red[0];

    // vcq_sum[a] = sum_q vcq[n,a,q]
    if (tid < AA) {
        const float* vp = vcq + ((size_t)n * AA + tid) * QQ;
        float s = 0.f;
#pragma unroll 4
        for (int q = 0; q < QQ; q++) s += vp[q];
        g_vcqsum[n * AA + tid] = s;
    }
}

// ---------------- prep: W1^T -> bf16 (tiled transpose) ---------------------
__global__ void k_prepw(const float* __restrict__ W1) {
    int n = blockIdx.y;
    int tile = blockIdx.x;              // 48 = (QQ/32) * (DD/32)
    int d0 = (tile % 6) * 32, q0 = (tile / 6) * 32;
    int tx = threadIdx.x, ty = threadIdx.y;   // (32, 8)
    __shared__ float tl[32][33];
#pragma unroll
    for (int j = 0; j < 4; j++)
        tl[ty + j * 8][tx] = W1[((size_t)n * DD + d0 + ty + j * 8) * QQ + q0 + tx];
    __syncthreads();
#pragma unroll
    for (int j = 0; j < 4; j++)
        g_w1t[((size_t)n * QQ + q0 + ty + j * 8) * DD + d0 + tx] =
            __float2bfloat16_rn(tl[tx][ty + j * 8]);
}

// ---------------- prep: query^T fp32 (tiled transpose) ---------------------
__global__ void k_prepq(const float* __restrict__ query) {
    int n = blockIdx.y;
    int tile = blockIdx.x;              // 48 = (QQ/32) * (AA/32)
    int a0 = (tile % 6) * 32, q0 = (tile / 6) * 32;
    int tx = threadIdx.x, ty = threadIdx.y;   // (32, 8)
    __shared__ float tl[32][33];
#pragma unroll
    for (int j = 0; j < 4; j++)
        tl[ty + j * 8][tx] = query[((size_t)n * QQ + q0 + ty + j * 8) * AA + a0 + tx];
    __syncthreads();
#pragma unroll
    for (int j = 0; j < 4; j++)
        g_qT[((size_t)n * AA + a0 + ty + j * 8) * QQ + q0 + tx] = tl[tx][ty + j * 8];
}

// ---------------- ctx-a: hck + t1 for all 16 b per block -------------------
// grid (8 qtiles, 8 n), block 256: thread = (qi 0..31, sl 0..7)
__global__ __launch_bounds__(256) void k_ctx_a(
        const float* __restrict__ uk_W, const float* __restrict__ u_q1W,
        const float* __restrict__ u_q1b,
        const float* __restrict__ bnc_g, const float* __restrict__ bnc_b,
        const float* __restrict__ bnc_m, const float* __restrict__ bnc_v) {
    int n = blockIdx.y, qt = blockIdx.x;
    int tid = threadIdx.x;
    int qi = tid & 31, sl = tid >> 5;
    int q = qt * 32 + qi;

    __shared__ float c_sh[16 * 384];
    __shared__ float part[8 * 16 * 33];

    for (int i = tid; i < 16 * 384; i += 256) {
        int b = i / 384, l = i - b * 384;
        c_sh[i] = g_c[((size_t)b * CC + n * DD) * 2 + l];
    }
    __syncthreads();

    float ak[16], aq[16];
#pragma unroll
    for (int b = 0; b < 16; b++) { ak[b] = 0.f; aq[b] = 0.f; }
    {
        const float* uk = uk_W + ((size_t)n * 384) * QQ + q;
        const float* u1 = u_q1W + ((size_t)n * 384) * QQ + q;
        int l0 = sl * 48;
        for (int l = l0; l < l0 + 48; l++) {
            float wk = uk[(size_t)l * QQ];
            float w1 = u1[(size_t)l * QQ];
            const float* cb = c_sh + l;
#pragma unroll
            for (int b = 0; b < 16; b++) {
                float cv = cb[b * 384];
                ak[b] = fmaf(cv, wk, ak[b]);
                aq[b] = fmaf(cv, w1, aq[b]);
            }
        }
    }

    // reduce hck
#pragma unroll
    for (int b = 0; b < 16; b++) part[(sl * 16 + b) * 33 + qi] = ak[b];
    __syncthreads();
    {
        int bp = tid >> 5;
        float s0 = 0.f, s1 = 0.f;
#pragma unroll
        for (int s = 0; s < 8; s++) {
            s0 += part[(s * 16 + bp) * 33 + qi];
            s1 += part[(s * 16 + bp + 8) * 33 + qi];
        }
        g_hck[((size_t)(bp * NH + n)) * QQ + q] = s0;
        g_hck[((size_t)((bp + 8) * NH + n)) * QQ + q] = s1;
    }
    __syncthreads();

    // reduce cq1 -> t1 activation
#pragma unroll
    for (int b = 0; b < 16; b++) part[(sl * 16 + b) * 33 + qi] = aq[b];
    __syncthreads();
    {
        int bp = tid >> 5;
        float s0 = 0.f, s1 = 0.f;
#pragma unroll
        for (int s = 0; s < 8; s++) {
            s0 += part[(s * 16 + bp) * 33 + qi];
            s1 += part[(s * 16 + bp + 8) * 33 + qi];
        }
        float bias = u_q1b[n * QQ + q];
        float grs = bnc_g[q] * rsqrtf(bnc_v[q] + 1e-5f);
        float beta = bnc_b[q] - grs * bnc_m[q];
        float r0 = fmaxf(s0 + bias, 0.f);
        float r1 = fmaxf(s1 + bias, 0.f);
        g_t1[((size_t)(bp * NH + n)) * QQ + q] = tanhf(fmaf(grs, r0, beta));
        g_t1[((size_t)((bp + 8) * NH + n)) * QQ + q] = tanhf(fmaf(grs, r1, beta));
    }
}

// ---------------- ctx-b: cq2 = t1 @ u_q2 for all 16 b per block ------------
// grid (6 atiles, 8 n), block 256: thread = (ai 0..31, msl 0..7)
__global__ __launch_bounds__(256) void k_ctx_b(const float* __restrict__ u_q2) {
    int n = blockIdx.y, at = blockIdx.x;
    int tid = threadIdx.x;
    int ai = tid & 31, msl = tid >> 5;
    int a = at * 32 + ai;

    __shared__ float t1_sh[16 * 256];
    __shared__ float part[8 * 16 * 33];

    for (int i = tid; i < 16 * 256; i += 256) {
        int b = i >> 8, m = i & 255;
        t1_sh[i] = g_t1[((size_t)(b * NH + n)) * QQ + m];
    }
    __syncthreads();

    float acc[16];
#pragma unroll
    for (int b = 0; b < 16; b++) acc[b] = 0.f;
    {
        const float* u2 = u_q2 + (size_t)n * QQ * AA + a;
        int m0 = msl * 32;
        for (int m = m0; m < m0 + 32; m++) {
            float w = u2[(size_t)m * AA];
            const float* tb = t1_sh + m;
#pragma unroll
            for (int b = 0; b < 16; b++)
                acc[b] = fmaf(tb[b * 256], w, acc[b]);
        }
    }
#pragma unroll
    for (int b = 0; b < 16; b++) part[(msl * 16 + b) * 33 + ai] = acc[b];
    __syncthreads();
    {
        int bp = tid >> 5;
        float s0 = 0.f, s1 = 0.f;
#pragma unroll
        for (int s = 0; s < 8; s++) {
            s0 += part[(s * 16 + bp) * 33 + ai];
            s1 += part[(s * 16 + bp + 8) * 33 + ai];
        }
        g_cq2[((size_t)(bp * NH + n)) * AA + a] = s0;
        g_cq2[((size_t)((bp + 8) * NH + n)) * AA + a] = s1;
    }
}

// ---------------- ctx-c: scalars + hcqT write (coalesced) ------------------
__global__ __launch_bounds__(256) void k_ctx_c(const float* __restrict__ vck) {
    int bn = blockIdx.x;
    int b = bn >> 3, n = bn & 7;
    int tid = threadIdx.x;
    (void)b;

    __shared__ float cq2_sh[AA];
    __shared__ float red[256];
    __shared__ float lamq_sh;

    if (tid < AA) cq2_sh[tid] = g_cq2[(size_t)bn * AA + tid];

    // ckdot
    red[tid] = g_hck[(size_t)bn * QQ + tid] * vck[n * QQ + tid];
    __syncthreads();
    for (int off = 128; off > 0; off >>= 1) {
        if (tid < off) red[tid] += red[tid + off];
        __syncthreads();
    }
    if (tid == 0) g_ckdot[bn] = red[0];
    __syncthreads();

    // vcqdot via vcq_sum
    red[tid] = (tid < AA) ? cq2_sh[tid] * g_vcqsum[n * AA + tid] : 0.f;
    __syncthreads();
    for (int off = 128; off > 0; off >>= 1) {
        if (tid < off) red[tid] += red[tid + off];
        __syncthreads();
    }
    if (tid == 0)
        lamq_sh = 1.f / (1.f + expf(-(g_qdot[n] + red[0])));
    __syncthreads();

    float lq = lamq_sh;
    const float inv_sq = 1.f / 16.f;  // 1/sqrt(Q)
    const float* qtp = g_qT + (size_t)n * AA * QQ + tid;
    __nv_bfloat16* op = g_hcqT + (size_t)bn * AA * QQ + tid;
#pragma unroll 4
    for (int a = 0; a < AA; a++) {
        float qv = qtp[(size_t)a * QQ];
        float v = (fmaf(lq, cq2_sh[a] - qv, qv)) * inv_sq;
        op[(size_t)a * QQ] = __float2bfloat16_rn(v);
    }
}

// ---------------- K3: warp-MMA fused scores kernel -------------------------
#define XS_STRIDE 200
#define HK_STRIDE 264
#define SM_XS 0
#define SM_HK 51200
#define SM_W1 118784
#define SM_AUX 144384
#define AXH_HCK  (SM_AUX + 0)
#define AXH_KBV  (SM_AUX + 1024)
#define AXH_GRS  (SM_AUX + 2048)
#define AXH_BETA (SM_AUX + 3072)
#define AXH_VHK  (SM_AUX + 4096)
#define AXH_QB   (SM_AUX + 5120)
#define AXH_LAM  (SM_AUX + 6144)
#define SMEM_SC  (SM_AUX + 6656)

__global__ __launch_bounds__(256) void k_scores_mma(
        const float* __restrict__ ht, const float* __restrict__ kb,
        const float* __restrict__ bg, const float* __restrict__ bbias,
        const float* __restrict__ bm, const float* __restrict__ bv,
        const float* __restrict__ vhk, const float* __restrict__ qb) {
    extern __shared__ char smem[];
    uint32_t sb = smem_u32(smem);
    int tid = threadIdx.x;
    int w = tid >> 5, lane = tid & 31;
    int bn = blockIdx.y;
    int b = bn >> 3, n = bn & 7;
    int t0 = blockIdx.x * 128;

    // aux constant arrays
    {
        int i = tid;  // 256 threads == QQ
        float g = bg[i];
        float grs = g * rsqrtf(bv[i] + 1e-5f);
        ((float*)(smem + AXH_GRS))[i] = grs;
        ((float*)(smem + AXH_BETA))[i] = bbias[i] - grs * bm[i];
        ((float*)(smem + AXH_HCK))[i] = g_hck[(size_t)bn * QQ + i];
        ((float*)(smem + AXH_KBV))[i] = kb[n * QQ + i];
        ((float*)(smem + AXH_VHK))[i] = vhk[n * QQ + i];
        if (i < AA) ((float*)(smem + AXH_QB))[i] = qb[n * AA + i];
    }

    // ---- load x tile (fp32 -> bf16), rows padded with zeros past TT ----
    {
        const float* xb = ht + ((size_t)b * TT + t0) * CC + n * DD;
        for (int it = 0; it < 24; it++) {
            int idx = it * 256 + tid;            // 128 rows x 48 float4
            int row = idx / 48, c4 = idx - row * 48;
            float4 v = make_float4(0.f, 0.f, 0.f, 0.f);
            if (t0 + row < TT) v = *(const float4*)(xb + (size_t)row * CC + c4 * 4);
            uint2 pk = make_uint2(pack_bf(v.x, v.y), pack_bf(v.z, v.w));
            *(uint2*)(smem + SM_XS + (row * XS_STRIDE + c4 * 4) * 2) = pk;
        }
    }

    uint32_t abase = sb + SM_XS + ((w * 16 + (lane & 15)) * XS_STRIDE + (lane >> 4) * 8) * 2;
    uint32_t bbase = sb + SM_W1 + (((lane >> 4) * 8 + (lane & 7)) * XS_STRIDE + ((lane >> 3) & 1) * 8) * 2;

    // ---- GEMM1 over 4 q-chunks of 64; lambda partials in-register ----
    float lam0 = 0.f, lam1 = 0.f;
    for (int qc = 0; qc < 4; qc++) {
        __syncthreads();
        {
            const uint4* wsrc = (const uint4*)(g_w1t + ((size_t)n * QQ + qc * 64) * DD);
            for (int it = 0; it < 6; it++) {
                int idx = it * 256 + tid;        // 64 rows x 24 uint4
                int row = idx / 24, c8 = idx - row * 24;
                *(uint4*)(smem + SM_W1 + (row * XS_STRIDE + c8 * 8) * 2) = wsrc[idx];
            }
        }
        __syncthreads();

        float c[4][2][4];
#pragma unroll
        for (int p = 0; p < 4; p++)
#pragma unroll
            for (int j = 0; j < 2; j++)
#pragma unroll
                for (int e = 0; e < 4; e++) c[p][j][e] = 0.f;

        for (int kk = 0; kk < 12; kk++) {
            uint32_t a[4];
            ldsm_x4(a, abase + kk * 32);
#pragma unroll
            for (int p = 0; p < 4; p++) {
                uint32_t bf[4];
                ldsm_x4(bf, bbase + p * 16 * XS_STRIDE * 2 + kk * 32);
                mma_bf16(c[p][0], a, bf[0], bf[1]);
                mma_bf16(c[p][1], a, bf[2], bf[3]);
            }
        }

        const float* vhk_s = (const float*)(smem + AXH_VHK);
        int r0 = w * 16 + (lane >> 2);
#pragma unroll
        for (int p = 0; p < 4; p++) {
#pragma unroll
            for (int j = 0; j < 2; j++) {
                int col = qc * 64 + p * 16 + j * 8 + 2 * (lane & 3);
                float v0 = vhk_s[col], v1 = vhk_s[col + 1];
                lam0 += c[p][j][0] * v0 + c[p][j][1] * v1;
                lam1 += c[p][j][2] * v0 + c[p][j][3] * v1;
                *(uint32_t*)(smem + SM_HK + (r0 * HK_STRIDE + col) * 2) =
                    pack_bf(c[p][j][0], c[p][j][1]);
                *(uint32_t*)(smem + SM_HK + ((r0 + 8) * HK_STRIDE + col) * 2) =
                    pack_bf(c[p][j][2], c[p][j][3]);
            }
        }
    }

    lam0 += __shfl_xor_sync(0xffffffffu, lam0, 1);
    lam0 += __shfl_xor_sync(0xffffffffu, lam0, 2);
    lam1 += __shfl_xor_sync(0xffffffffu, lam1, 1);
    lam1 += __shfl_xor_sync(0xffffffffu, lam1, 2);
    {
        float ckd = g_ckdot[bn];
        if ((lane & 3) == 0) {
            float* lam_sh = (float*)(smem + AXH_LAM);
            lam_sh[w * 16 + (lane >> 2)] = 1.f / (1.f + expf(-(lam0 + ckd)));
            lam_sh[w * 16 + (lane >> 2) + 8] = 1.f / (1.f + expf(-(lam1 + ckd)));
        }
    }
    __syncthreads();

    // ---- activation in place ----
    {
        int row = w * 16 + (lane >> 1);
        int cb = (lane & 1) * 128;
        float lam = ((const float*)(smem + AXH_LAM))[row];
        const float* hck_s = (const float*)(smem + AXH_HCK);
        const float* kbv_s = (const float*)(smem + AXH_KBV);
        const float* grs_s = (const float*)(smem + AXH_GRS);
        const float* bet_s = (const float*)(smem + AXH_BETA);
        uint32_t* hp = (uint32_t*)(smem + SM_HK + (row * HK_STRIDE + cb) * 2);
        for (int j = 0; j < 16; j++) {
            uint4 v = *(uint4*)(hp + j * 4);
            uint32_t* vr = (uint32_t*)&v;
#pragma unroll
            for (int e = 0; e < 4; e++) {
                int c0 = cb + j * 8 + 2 * e;
                float h0 = bflo(vr[e]), h1 = bfhi(vr[e]);
                float m0 = fmaf(lam, hck_s[c0] - h0, h0) + kbv_s[c0];
                float m1 = fmaf(lam, hck_s[c0 + 1] - h1, h1) + kbv_s[c0 + 1];
                m0 = fmaxf(m0, 0.f); m1 = fmaxf(m1, 0.f);
                float a0 = tanha(fmaf(grs_s[c0], m0, bet_s[c0]));
                float a1 = tanha(fmaf(grs_s[c0 + 1], m1, bet_s[c0 + 1]));
                vr[e] = pack_bf(a0, a1);
            }
            *(uint4*)(hp + j * 4) = v;
        }
    }

    // ---- GEMM2 over 2 a-chunks of 96 ----
    uint32_t abase2 = sb + SM_HK + ((w * 16 + (lane & 15)) * HK_STRIDE + (lane >> 4) * 8) * 2;
    uint32_t bbase2 = sb + SM_XS + (((lane >> 4) * 8 + (lane & 7)) * HK_STRIDE + ((lane >> 3) & 1) * 8) * 2;
    int r0 = w * 16 + (lane >> 2);
    int t_a = t0 + r0, t_b = t0 + r0 + 8;
    const float* qb_s = (const float*)(smem + AXH_QB);

    for (int ac = 0; ac < 2; ac++) {
        __syncthreads();
        {
            const uint4* hs = (const uint4*)(g_hcqT + ((size_t)bn * AA + ac * 96) * QQ);
            for (int it = 0; it < 12; it++) {
                int idx = it * 256 + tid;        // 96 rows x 32 uint4
                int row = idx / 32, c8 = idx - row * 32;
                *(uint4*)(smem + SM_XS + (row * HK_STRIDE + c8 * 8) * 2) = hs[idx];
            }
        }
        __syncthreads();

        float c2[6][2][4];
#pragma unroll
        for (int p = 0; p < 6; p++)
#pragma unroll
            for (int j = 0; j < 2; j++)
#pragma unroll
                for (int e = 0; e < 4; e++) c2[p][j][e] = 0.f;

        for (int kk = 0; kk < 16; kk++) {
            uint32_t a[4];
            ldsm_x4(a, abase2 + kk * 32);
#pragma unroll
            for (int p = 0; p < 6; p++) {
                uint32_t bf[4];
                ldsm_x4(bf, bbase2 + p * 16 * HK_STRIDE * 2 + kk * 32);
                mma_bf16(c2[p][0], a, bf[0], bf[1]);
                mma_bf16(c2[p][1], a, bf[2], bf[3]);
            }
        }

#pragma unroll
        for (int p = 0; p < 6; p++) {
#pragma unroll
            for (int j = 0; j < 2; j++) {
                int col = ac * 96 + p * 16 + j * 8 + 2 * (lane & 3);
                float q0 = qb_s[col], q1 = qb_s[col + 1];
                if (t_a < TT) {
                    float2 v = make_float2(c2[p][j][0] + q0, c2[p][j][1] + q1);
                    *(float2*)(g_scores + (((size_t)b * TT + t_a) * NH + n) * AA + col) = v;
                }
                if (t_b < TT) {
                    float2 v = make_float2(c2[p][j][2] + q0, c2[p][j][3] + q1);
                    *(float2*)(g_scores + (((size_t)b * TT + t_b) * NH + n) * AA + col) = v;
                }
            }
        }
    }
}

// ---------------- K4: softmax over T + weighted mean/std pooling ----------
__global__ void k_pool(const float* __restrict__ ht, float* __restrict__ out) {
    int bn = blockIdx.x;
    int b = bn >> 3, n = bn & 7;
    int a = threadIdx.x;
    int chunk = threadIdx.y;
    const int CH = TT / 4;  // 500
    int ts = chunk * CH, te = ts + CH;

    float m = -1e30f, Z = 0.f, S1 = 0.f, S2 = 0.f;
    const float* sc = g_scores + ((size_t)b * TT * NH + n) * AA + a;
    const float* vp = ht + (size_t)b * TT * CC + n * DD + a;
    for (int t = ts; t < te; t++) {
        float s = sc[(size_t)t * NH * AA];
        float v = vp[(size_t)t * CC];
        float nm = fmaxf(m, s);
        float cc = expf(m - nm);
        float w = expf(s - nm);
        Z = Z * cc + w;
        S1 = S1 * cc + w * v;
        S2 = S2 * cc + w * v * v;
        m = nm;
    }
    __shared__ float shm[4][AA], shZ[4][AA], sh1[4][AA], sh2[4][AA];
    shm[chunk][a] = m; shZ[chunk][a] = Z; sh1[chunk][a] = S1; sh2[chunk][a] = S2;
    __syncthreads();
    if (chunk == 0) {
        float M = shm[0][a];
        for (int j = 1; j < 4; j++) M = fmaxf(M, shm[j][a]);
        float Zt = 0.f, S1t = 0.f, S2t = 0.f;
        for (int j = 0; j < 4; j++) {
            float c = expf(shm[j][a] - M);
            Zt += shZ[j][a] * c; S1t += sh1[j][a] * c; S2t += sh2[j][a] * c;
        }
        float mu = S1t / Zt;
        float ex2 = S2t / Zt;
        float rh = sqrtf(fmaxf(ex2 - mu * mu, 1e-9f));
        out[(size_t)b * (2 * CC) + n * DD + a] = mu;
        out[(size_t)b * (2 * CC) + CC + n * DD + a] = rh;
    }
}

// ---------------- launcher ------------------------------------------------
extern "C" void kernel_launch(void* const* d_in, const int* in_sizes, int n_in,
                              void* d_out, int out_size) {
    const float* ht       = (const float*)d_in[0];
    const float* k_proj_W = (const float*)d_in[1];
    const float* query    = (const float*)d_in[2];
    const float* uk_W     = (const float*)d_in[3];
    const float* u_q1W    = (const float*)d_in[4];
    const float* u_q2     = (const float*)d_in[5];
    const float* vhq      = (const float*)d_in[6];
    const float* vhk      = (const float*)d_in[7];
    const float* vcq      = (const float*)d_in[8];
    const float* vck      = (const float*)d_in[9];
    const float* k_proj_b = (const float*)d_in[10];
    const float* q_b      = (const float*)d_in[11];
    const float* u_q1b    = (const float*)d_in[12];
    const float* bnc_g    = (const float*)d_in[13];
    const float* bnc_b    = (const float*)d_in[14];
    const float* bnc_m    = (const float*)d_in[15];
    const float* bnc_v    = (const float*)d_in[16];
    const float* bnk_g    = (const float*)d_in[17];
    const float* bnk_b    = (const float*)d_in[18];
    const float* bnk_m    = (const float*)d_in[19];
    const float* bnk_v    = (const float*)d_in[20];
    float* out = (float*)d_out;

    static int smem_set = 0;
    if (!smem_set) {
        cudaFuncSetAttribute(k_scores_mma,
                             cudaFuncAttributeMaxDynamicSharedMemorySize, SMEM_SC);
        smem_set = 1;
    }

    dim3 gs(CC / 128, BB);
    dim3 bs(128, 8);
    k_stats<<<gs, bs>>>(ht);

    dim3 gt(48, NH), bt(32, 8);
    k_prepw<<<gt, bt>>>(k_proj_W);
    k_prepq<<<gt, bt>>>(query);
    k_qdot<<<NH, 256>>>(query, vhq, vcq);

    dim3 ga(8, NH);
    k_ctx_a<<<ga, 256>>>(uk_W, u_q1W, u_q1b, bnc_g, bnc_b, bnc_m, bnc_v);
    dim3 gb(6, NH);
    k_ctx_b<<<gb, 256>>>(u_q2);
    k_ctx_c<<<BB * NH, 256>>>(vck);

    dim3 gsc(16, BB * NH);
    k_scores_mma<<<gsc, 256, SMEM_SC>>>(ht, k_proj_b, bnk_g, bnk_b, bnk_m, bnk_v,
                                        vhk, q_b);

    dim3 bp(AA, 4);
    k_pool<<<BB * NH, bp>>>(ht, out);
}

// round 7
// speedup vs baseline: 4.4555x; 1.2675x over previous
#include <cuda_runtime.h>
#include <cuda_bf16.h>
#include <math.h>
#include <stdint.h>

// Problem constants
#define BB 16
#define TT 2000
#define CC 1536
#define NH 8
#define DD 192
#define QQ 256
#define AA 192

// ===================== warp-MMA helpers (sm_80+ baseline, no 'a' gate) =====
__device__ __forceinline__ uint32_t smem_u32(const void* p) {
    uint32_t a;
    asm("{ .reg .u64 t; cvta.to.shared.u64 t, %1; cvt.u32.u64 %0, t; }"
        : "=r"(a) : "l"(p));
    return a;
}
__device__ __forceinline__ void ldsm_x4(uint32_t r[4], uint32_t addr) {
    asm volatile("ldmatrix.sync.aligned.m8n8.x4.shared.b16 {%0,%1,%2,%3}, [%4];"
                 : "=r"(r[0]), "=r"(r[1]), "=r"(r[2]), "=r"(r[3]) : "r"(addr));
}
__device__ __forceinline__ void mma_bf16(float c[4], const uint32_t a[4],
                                         uint32_t b0, uint32_t b1) {
    asm volatile("mma.sync.aligned.m16n8k16.row.col.f32.bf16.bf16.f32 "
                 "{%0,%1,%2,%3}, {%4,%5,%6,%7}, {%8,%9}, {%0,%1,%2,%3};"
                 : "+f"(c[0]), "+f"(c[1]), "+f"(c[2]), "+f"(c[3])
                 : "r"(a[0]), "r"(a[1]), "r"(a[2]), "r"(a[3]), "r"(b0), "r"(b1));
}
__device__ __forceinline__ uint32_t pack_bf(float lo, float hi) {
    uint32_t r;
    asm("cvt.rn.bf16x2.f32 %0, %1, %2;" : "=r"(r) : "f"(hi), "f"(lo));
    return r;
}
__device__ __forceinline__ float bflo(uint32_t u) { return __uint_as_float(u << 16); }
__device__ __forceinline__ float bfhi(uint32_t u) { return __uint_as_float(u & 0xffff0000u); }
__device__ __forceinline__ float tanha(float x) {
    float r; asm("tanh.approx.f32 %0, %1;" : "=f"(r) : "f"(x)); return r;
}
#define CP_ASYNC16(dst, src) \
    asm volatile("cp.async.cg.shared.global [%0], [%1], 16;" :: "r"(dst), "l"(src))
#define CP_COMMIT() asm volatile("cp.async.commit_group;" ::: "memory")
#define CP_WAIT0() asm volatile("cp.async.wait_group 0;" ::: "memory")
#define CP_WAIT1() asm volatile("cp.async.wait_group 1;" ::: "memory")

// ---------------- scratch (device globals: no allocations allowed) --------
__device__ float g_c[BB * CC * 2];
__device__ float g_hck[BB * NH * QQ];
__device__ float g_t1[BB * NH * QQ];
__device__ float g_cq2[BB * NH * AA];
__device__ float g_vcqsum[NH * AA];
__device__ float g_ckdot[BB * NH];
__device__ float g_qdotp[NH * 8];
__device__ float g_qT[NH * AA * QQ];                          // query^T [n][a][q]
__device__ __nv_bfloat16 g_w1t[NH * QQ * DD];                 // W1^T [n][q][d] bf16
__device__ __nv_bfloat16 g_hcqT[(size_t)BB * NH * AA * QQ];   // hcq^T/sqrt(Q) [bn][a][q]
__device__ float g_scores[(size_t)BB * TT * NH * AA];         // [b][t][n][a]
__device__ float4 g_pp[BB * NH * 8 * AA];                     // pool partials

// ---------------- K1: mean/std over time ----------------------------------
__global__ void k_stats(const float* __restrict__ ht) {
    int b = blockIdx.y;
    int ch = blockIdx.x * 128 + threadIdx.x;
    int ty = threadIdx.y;
    float s = 0.f, s2 = 0.f;
    const float* p = ht + (size_t)b * TT * CC + ch;
    for (int t = ty; t < TT; t += 8) {
        float v = p[(size_t)t * CC];
        s += v; s2 += v * v;
    }
    __shared__ float sh0[8][128];
    __shared__ float sh1[8][128];
    sh0[ty][threadIdx.x] = s;
    sh1[ty][threadIdx.x] = s2;
    __syncthreads();
    if (ty == 0) {
        for (int j = 1; j < 8; j++) { s += sh0[j][threadIdx.x]; s2 += sh1[j][threadIdx.x]; }
        float mean = s * (1.f / TT);
        float var = (s2 - (float)TT * mean * mean) * (1.f / (TT - 1));
        float sd = sqrtf(fmaxf(var, 0.f));
        g_c[((size_t)b * CC + ch) * 2 + 0] = mean;
        g_c[((size_t)b * CC + ch) * 2 + 1] = sd;
    }
}

// ---------------- K0: qdot partials + vcq_sum (parallel over 64 blocks) ---
__global__ void k_qdot(const float* __restrict__ query, const float* __restrict__ vhq,
                       const float* __restrict__ vcq) {
    int s = blockIdx.x;     // 0..7 slice
    int n = blockIdx.y;
    int tid = threadIdx.x;
    float acc = 0.f;
    int base = s * (AA * QQ / 8);      // 6144
    for (int ii = tid; ii < AA * QQ / 8; ii += 256) {
        int i = base + ii;
        int a = i >> 8, q = i & 255;
        acc += query[(n * QQ + q) * AA + a] * vhq[n * AA * QQ + i];
    }
    __shared__ float red[256];
    red[tid] = acc;
    __syncthreads();
    for (int off = 128; off > 0; off >>= 1) {
        if (tid < off) red[tid] += red[tid + off];
        __syncthreads();
    }
    if (tid == 0) g_qdotp[n * 8 + s] = red[0];

    // vcq_sum for 24 a-rows: warp per row
    int w = tid >> 5, lane = tid & 31;
    for (int r = w; r < AA / 8; r += 8) {
        int a = s * (AA / 8) + r;
        const float* vp = vcq + ((size_t)n * AA + a) * QQ;
        float sum = 0.f;
        for (int q = lane; q < QQ; q += 32) sum += vp[q];
#pragma unroll
        for (int o = 16; o > 0; o >>= 1) sum += __shfl_down_sync(0xffffffffu, sum, o);
        if (lane == 0) g_vcqsum[n * AA + a] = sum;
    }
}

// ---------------- prep: W1^T -> bf16 (tiled transpose) ---------------------
__global__ void k_prepw(const float* __restrict__ W1) {
    int n = blockIdx.y;
    int tile = blockIdx.x;              // 48 = (QQ/32) * (DD/32)
    int d0 = (tile % 6) * 32, q0 = (tile / 6) * 32;
    int tx = threadIdx.x, ty = threadIdx.y;   // (32, 8)
    __shared__ float tl[32][33];
#pragma unroll
    for (int j = 0; j < 4; j++)
        tl[ty + j * 8][tx] = W1[((size_t)n * DD + d0 + ty + j * 8) * QQ + q0 + tx];
    __syncthreads();
#pragma unroll
    for (int j = 0; j < 4; j++)
        g_w1t[((size_t)n * QQ + q0 + ty + j * 8) * DD + d0 + tx] =
            __float2bfloat16_rn(tl[tx][ty + j * 8]);
}

// ---------------- prep: query^T fp32 (tiled transpose) ---------------------
__global__ void k_prepq(const float* __restrict__ query) {
    int n = blockIdx.y;
    int tile = blockIdx.x;              // 48 = (QQ/32) * (AA/32)
    int a0 = (tile % 6) * 32, q0 = (tile / 6) * 32;
    int tx = threadIdx.x, ty = threadIdx.y;   // (32, 8)
    __shared__ float tl[32][33];
#pragma unroll
    for (int j = 0; j < 4; j++)
        tl[ty + j * 8][tx] = query[((size_t)n * QQ + q0 + ty + j * 8) * AA + a0 + tx];
    __syncthreads();
#pragma unroll
    for (int j = 0; j < 4; j++)
        g_qT[((size_t)n * AA + a0 + ty + j * 8) * QQ + q0 + tx] = tl[tx][ty + j * 8];
}

// ---------------- ctx-a: hck + t1 for all 16 b per block -------------------
__global__ __launch_bounds__(256) void k_ctx_a(
        const float* __restrict__ uk_W, const float* __restrict__ u_q1W,
        const float* __restrict__ u_q1b,
        const float* __restrict__ bnc_g, const float* __restrict__ bnc_b,
        const float* __restrict__ bnc_m, const float* __restrict__ bnc_v) {
    int n = blockIdx.y, qt = blockIdx.x;
    int tid = threadIdx.x;
    int qi = tid & 31, sl = tid >> 5;
    int q = qt * 32 + qi;

    __shared__ float c_sh[16 * 384];
    __shared__ float part[8 * 16 * 33];

    for (int i = tid; i < 16 * 384; i += 256) {
        int b = i / 384, l = i - b * 384;
        c_sh[i] = g_c[((size_t)b * CC + n * DD) * 2 + l];
    }
    __syncthreads();

    float ak[16], aq[16];
#pragma unroll
    for (int b = 0; b < 16; b++) { ak[b] = 0.f; aq[b] = 0.f; }
    {
        const float* uk = uk_W + ((size_t)n * 384) * QQ + q;
        const float* u1 = u_q1W + ((size_t)n * 384) * QQ + q;
        int l0 = sl * 48;
        for (int l = l0; l < l0 + 48; l++) {
            float wk = uk[(size_t)l * QQ];
            float w1 = u1[(size_t)l * QQ];
            const float* cb = c_sh + l;
#pragma unroll
            for (int b = 0; b < 16; b++) {
                float cv = cb[b * 384];
                ak[b] = fmaf(cv, wk, ak[b]);
                aq[b] = fmaf(cv, w1, aq[b]);
            }
        }
    }

#pragma unroll
    for (int b = 0; b < 16; b++) part[(sl * 16 + b) * 33 + qi] = ak[b];
    __syncthreads();
    {
        int bp = tid >> 5;
        float s0 = 0.f, s1 = 0.f;
#pragma unroll
        for (int s = 0; s < 8; s++) {
            s0 += part[(s * 16 + bp) * 33 + qi];
            s1 += part[(s * 16 + bp + 8) * 33 + qi];
        }
        g_hck[((size_t)(bp * NH + n)) * QQ + q] = s0;
        g_hck[((size_t)((bp + 8) * NH + n)) * QQ + q] = s1;
    }
    __syncthreads();

#pragma unroll
    for (int b = 0; b < 16; b++) part[(sl * 16 + b) * 33 + qi] = aq[b];
    __syncthreads();
    {
        int bp = tid >> 5;
        float s0 = 0.f, s1 = 0.f;
#pragma unroll
        for (int s = 0; s < 8; s++) {
            s0 += part[(s * 16 + bp) * 33 + qi];
            s1 += part[(s * 16 + bp + 8) * 33 + qi];
        }
        float bias = u_q1b[n * QQ + q];
        float grs = bnc_g[q] * rsqrtf(bnc_v[q] + 1e-5f);
        float beta = bnc_b[q] - grs * bnc_m[q];
        float r0 = fmaxf(s0 + bias, 0.f);
        float r1 = fmaxf(s1 + bias, 0.f);
        g_t1[((size_t)(bp * NH + n)) * QQ + q] = tanhf(fmaf(grs, r0, beta));
        g_t1[((size_t)((bp + 8) * NH + n)) * QQ + q] = tanhf(fmaf(grs, r1, beta));
    }
}

// ---------------- ctx-b: cq2 = t1 @ u_q2 for all 16 b per block ------------
__global__ __launch_bounds__(256) void k_ctx_b(const float* __restrict__ u_q2) {
    int n = blockIdx.y, at = blockIdx.x;
    int tid = threadIdx.x;
    int ai = tid & 31, msl = tid >> 5;
    int a = at * 32 + ai;

    __shared__ float t1_sh[16 * 256];
    __shared__ float part[8 * 16 * 33];

    for (int i = tid; i < 16 * 256; i += 256) {
        int b = i >> 8, m = i & 255;
        t1_sh[i] = g_t1[((size_t)(b * NH + n)) * QQ + m];
    }
    __syncthreads();

    float acc[16];
#pragma unroll
    for (int b = 0; b < 16; b++) acc[b] = 0.f;
    {
        const float* u2 = u_q2 + (size_t)n * QQ * AA + a;
        int m0 = msl * 32;
        for (int m = m0; m < m0 + 32; m++) {
            float w = u2[(size_t)m * AA];
            const float* tb = t1_sh + m;
#pragma unroll
            for (int b = 0; b < 16; b++)
                acc[b] = fmaf(tb[b * 256], w, acc[b]);
        }
    }
#pragma unroll
    for (int b = 0; b < 16; b++) part[(msl * 16 + b) * 33 + ai] = acc[b];
    __syncthreads();
    {
        int bp = tid >> 5;
        float s0 = 0.f, s1 = 0.f;
#pragma unroll
        for (int s = 0; s < 8; s++) {
            s0 += part[(s * 16 + bp) * 33 + ai];
            s1 += part[(s * 16 + bp + 8) * 33 + ai];
        }
        g_cq2[((size_t)(bp * NH + n)) * AA + a] = s0;
        g_cq2[((size_t)((bp + 8) * NH + n)) * AA + a] = s1;
    }
}

// ---------------- ctx-c: scalars + hcqT write (coalesced) ------------------
__global__ __launch_bounds__(256) void k_ctx_c(const float* __restrict__ vck) {
    int bn = blockIdx.x;
    int n = bn & 7;
    int tid = threadIdx.x;

    __shared__ float cq2_sh[AA];
    __shared__ float red[256];
    __shared__ float lamq_sh;

    if (tid < AA) cq2_sh[tid] = g_cq2[(size_t)bn * AA + tid];

    // ckdot
    red[tid] = g_hck[(size_t)bn * QQ + tid] * vck[n * QQ + tid];
    __syncthreads();
    for (int off = 128; off > 0; off >>= 1) {
        if (tid < off) red[tid] += red[tid + off];
        __syncthreads();
    }
    if (tid == 0) g_ckdot[bn] = red[0];
    __syncthreads();

    // vcqdot via vcq_sum
    red[tid] = (tid < AA) ? cq2_sh[tid] * g_vcqsum[n * AA + tid] : 0.f;
    __syncthreads();
    for (int off = 128; off > 0; off >>= 1) {
        if (tid < off) red[tid] += red[tid + off];
        __syncthreads();
    }
    if (tid == 0) {
        float qd = 0.f;
#pragma unroll
        for (int k = 0; k < 8; k++) qd += g_qdotp[n * 8 + k];
        lamq_sh = 1.f / (1.f + __expf(-(qd + red[0])));
    }
    __syncthreads();

    float lq = lamq_sh;
    const float inv_sq = 1.f / 16.f;  // 1/sqrt(Q)
    const float* qtp = g_qT + (size_t)n * AA * QQ + tid;
    __nv_bfloat16* op = g_hcqT + (size_t)bn * AA * QQ + tid;
#pragma unroll 4
    for (int a = 0; a < AA; a++) {
        float qv = qtp[(size_t)a * QQ];
        float v = (fmaf(lq, cq2_sh[a] - qv, qv)) * inv_sq;
        op[(size_t)a * QQ] = __float2bfloat16_rn(v);
    }
}

// ---------------- K3: warp-MMA fused scores kernel (cp.async pipelined) ----
#define XS_STRIDE 200
#define HK_STRIDE 264
#define SM_XS 0
#define SM_HK 51200
#define SM_W1A 118784
#define SM_W1B 144384
#define SM_AUX 169984
#define AXH_HCK  (SM_AUX + 0)
#define AXH_KBV  (SM_AUX + 1024)
#define AXH_GRS  (SM_AUX + 2048)
#define AXH_BETA (SM_AUX + 3072)
#define AXH_VHK  (SM_AUX + 4096)
#define AXH_QB   (SM_AUX + 5120)
#define AXH_LAM  (SM_AUX + 6144)
#define SMEM_SC  (SM_AUX + 6656)

__global__ __launch_bounds__(256) void k_scores_mma(
        const float* __restrict__ ht, const float* __restrict__ kb,
        const float* __restrict__ bg, const float* __restrict__ bbias,
        const float* __restrict__ bm, const float* __restrict__ bv,
        const float* __restrict__ vhk, const float* __restrict__ qb) {
    extern __shared__ char smem[];
    uint32_t sb = smem_u32(smem);
    int tid = threadIdx.x;
    int w = tid >> 5, lane = tid & 31;
    int bn = blockIdx.y;
    int b = bn >> 3, n = bn & 7;
    int t0 = blockIdx.x * 128;

    // kick off W1 chunk 0 async load immediately
    {
        const uint4* wsrc = (const uint4*)(g_w1t + (size_t)n * QQ * DD);
#pragma unroll
        for (int it = 0; it < 6; it++) {
            int idx = it * 256 + tid;
            int row = idx / 24, c8 = idx - row * 24;
            CP_ASYNC16(sb + SM_W1A + (row * XS_STRIDE + c8 * 8) * 2, wsrc + idx);
        }
        CP_COMMIT();
    }

    // aux constant arrays
    {
        int i = tid;
        float g = bg[i];
        float grs = g * rsqrtf(bv[i] + 1e-5f);
        ((float*)(smem + AXH_GRS))[i] = grs;
        ((float*)(smem + AXH_BETA))[i] = bbias[i] - grs * bm[i];
        ((float*)(smem + AXH_HCK))[i] = g_hck[(size_t)bn * QQ + i];
        ((float*)(smem + AXH_KBV))[i] = kb[n * QQ + i];
        ((float*)(smem + AXH_VHK))[i] = vhk[n * QQ + i];
        if (i < AA) ((float*)(smem + AXH_QB))[i] = qb[n * AA + i];
    }

    // ---- load x tile (fp32 -> bf16), rows padded with zeros past TT ----
    {
        const float* xb = ht + ((size_t)b * TT + t0) * CC + n * DD;
        for (int it = 0; it < 24; it++) {
            int idx = it * 256 + tid;            // 128 rows x 48 float4
            int row = idx / 48, c4 = idx - row * 48;
            float4 v = make_float4(0.f, 0.f, 0.f, 0.f);
            if (t0 + row < TT) v = *(const float4*)(xb + (size_t)row * CC + c4 * 4);
            uint2 pk = make_uint2(pack_bf(v.x, v.y), pack_bf(v.z, v.w));
            *(uint2*)(smem + SM_XS + (row * XS_STRIDE + c4 * 4) * 2) = pk;
        }
    }

    uint32_t abase = sb + SM_XS + ((w * 16 + (lane & 15)) * XS_STRIDE + (lane >> 4) * 8) * 2;
    uint32_t boff_w1 = (((lane >> 4) * 8 + (lane & 7)) * XS_STRIDE + ((lane >> 3) & 1) * 8) * 2;

    // ---- GEMM1 over 4 q-chunks of 64, double-buffered W1; lambda in regs --
    float lam0 = 0.f, lam1 = 0.f;
    for (int qc = 0; qc < 4; qc++) {
        if (qc < 3) {
            int buf = ((qc + 1) & 1) ? SM_W1B : SM_W1A;
            const uint4* wsrc = (const uint4*)(g_w1t + ((size_t)n * QQ + (qc + 1) * 64) * DD);
#pragma unroll
            for (int it = 0; it < 6; it++) {
                int idx = it * 256 + tid;
                int row = idx / 24, c8 = idx - row * 24;
                CP_ASYNC16(sb + buf + (row * XS_STRIDE + c8 * 8) * 2, wsrc + idx);
            }
            CP_COMMIT();
            CP_WAIT1();
        } else {
            CP_WAIT0();
        }
        __syncthreads();   // chunk qc resident; also guards buffer reuse

        uint32_t bbase = sb + ((qc & 1) ? SM_W1B : SM_W1A) + boff_w1;

        float c[4][2][4];
#pragma unroll
        for (int p = 0; p < 4; p++)
#pragma unroll
            for (int j = 0; j < 2; j++)
#pragma unroll
                for (int e = 0; e < 4; e++) c[p][j][e] = 0.f;

        for (int kk = 0; kk < 12; kk++) {
            uint32_t a[4];
            ldsm_x4(a, abase + kk * 32);
#pragma unroll
            for (int p = 0; p < 4; p++) {
                uint32_t bf[4];
                ldsm_x4(bf, bbase + p * 16 * XS_STRIDE * 2 + kk * 32);
                mma_bf16(c[p][0], a, bf[0], bf[1]);
                mma_bf16(c[p][1], a, bf[2], bf[3]);
            }
        }

        const float* vhk_s = (const float*)(smem + AXH_VHK);
        int r0 = w * 16 + (lane >> 2);
#pragma unroll
        for (int p = 0; p < 4; p++) {
#pragma unroll
            for (int j = 0; j < 2; j++) {
                int col = qc * 64 + p * 16 + j * 8 + 2 * (lane & 3);
                float v0 = vhk_s[col], v1 = vhk_s[col + 1];
                lam0 += c[p][j][0] * v0 + c[p][j][1] * v1;
                lam1 += c[p][j][2] * v0 + c[p][j][3] * v1;
                *(uint32_t*)(smem + SM_HK + (r0 * HK_STRIDE + col) * 2) =
                    pack_bf(c[p][j][0], c[p][j][1]);
                *(uint32_t*)(smem + SM_HK + ((r0 + 8) * HK_STRIDE + col) * 2) =
                    pack_bf(c[p][j][2], c[p][j][3]);
            }
        }
        __syncthreads();   // all reads of buf[qc] done before it is rewritten
    }

    // prefetch hcq chunk 0 into XS region (xs dead after GEMM1)
    {
        const uint4* hs = (const uint4*)(g_hcqT + (size_t)bn * AA * QQ);
#pragma unroll
        for (int it = 0; it < 12; it++) {
            int idx = it * 256 + tid;            // 96 rows x 32 uint4
            int row = idx / 32, c8 = idx - row * 32;
            CP_ASYNC16(sb + SM_XS + (row * HK_STRIDE + c8 * 8) * 2, hs + idx);
        }
        CP_COMMIT();
    }

    // lambda finalize
    lam0 += __shfl_xor_sync(0xffffffffu, lam0, 1);
    lam0 += __shfl_xor_sync(0xffffffffu, lam0, 2);
    lam1 += __shfl_xor_sync(0xffffffffu, lam1, 1);
    lam1 += __shfl_xor_sync(0xffffffffu, lam1, 2);
    {
        float ckd = g_ckdot[bn];
        if ((lane & 3) == 0) {
            float* lam_sh = (float*)(smem + AXH_LAM);
            lam_sh[w * 16 + (lane >> 2)] = 1.f / (1.f + __expf(-(lam0 + ckd)));
            lam_sh[w * 16 + (lane >> 2) + 8] = 1.f / (1.f + __expf(-(lam1 + ckd)));
        }
    }
    __syncthreads();

    // ---- activation in place (overlaps hcq chunk0 cp.async) ----
    {
        int row = w * 16 + (lane >> 1);
        int cb = (lane & 1) * 128;
        float lam = ((const float*)(smem + AXH_LAM))[row];
        const float* hck_s = (const float*)(smem + AXH_HCK);
        const float* kbv_s = (const float*)(smem + AXH_KBV);
        const float* grs_s = (const float*)(smem + AXH_GRS);
        const float* bet_s = (const float*)(smem + AXH_BETA);
        uint32_t* hp = (uint32_t*)(smem + SM_HK + (row * HK_STRIDE + cb) * 2);
        for (int j = 0; j < 16; j++) {
            uint4 v = *(uint4*)(hp + j * 4);
            uint32_t* vr = (uint32_t*)&v;
#pragma unroll
            for (int e = 0; e < 4; e++) {
                int c0 = cb + j * 8 + 2 * e;
                float h0 = bflo(vr[e]), h1 = bfhi(vr[e]);
                float m0 = fmaf(lam, hck_s[c0] - h0, h0) + kbv_s[c0];
                float m1 = fmaf(lam, hck_s[c0 + 1] - h1, h1) + kbv_s[c0 + 1];
                m0 = fmaxf(m0, 0.f); m1 = fmaxf(m1, 0.f);
                float a0 = tanha(fmaf(grs_s[c0], m0, bet_s[c0]));
                float a1 = tanha(fmaf(grs_s[c0 + 1], m1, bet_s[c0 + 1]));
                vr[e] = pack_bf(a0, a1);
            }
            *(uint4*)(hp + j * 4) = v;
        }
    }

    // ---- GEMM2 over 2 a-chunks of 96 (hcq chunk0 in XS, chunk1 in W1) ----
    uint32_t abase2 = sb + SM_HK + ((w * 16 + (lane & 15)) * HK_STRIDE + (lane >> 4) * 8) * 2;
    uint32_t boff_hcq = (((lane >> 4) * 8 + (lane & 7)) * HK_STRIDE + ((lane >> 3) & 1) * 8) * 2;
    int r0 = w * 16 + (lane >> 2);
    int t_a = t0 + r0, t_b = t0 + r0 + 8;
    const float* qb_s = (const float*)(smem + AXH_QB);

    for (int ac = 0; ac < 2; ac++) {
        if (ac == 0) {
            const uint4* hs = (const uint4*)(g_hcqT + ((size_t)bn * AA + 96) * QQ);
#pragma unroll
            for (int it = 0; it < 12; it++) {
                int idx = it * 256 + tid;
                int row = idx / 32, c8 = idx - row * 32;
                CP_ASYNC16(sb + SM_W1A + (row * HK_STRIDE + c8 * 8) * 2, hs + idx);
            }
            CP_COMMIT();
            CP_WAIT1();
        } else {
            CP_WAIT0();
        }
        __syncthreads();

        uint32_t bbase2 = sb + (ac ? SM_W1A : SM_XS) + boff_hcq;

        float c2[6][2][4];
#pragma unroll
        for (int p = 0; p < 6; p++)
#pragma unroll
            for (int j = 0; j < 2; j++)
#pragma unroll
                for (int e = 0; e < 4; e++) c2[p][j][e] = 0.f;

        for (int kk = 0; kk < 16; kk++) {
            uint32_t a[4];
            ldsm_x4(a, abase2 + kk * 32);
#pragma unroll
            for (int p = 0; p < 6; p++) {
                uint32_t bf[4];
                ldsm_x4(bf, bbase2 + p * 16 * HK_STRIDE * 2 + kk * 32);
                mma_bf16(c2[p][0], a, bf[0], bf[1]);
                mma_bf16(c2[p][1], a, bf[2], bf[3]);
            }
        }

#pragma unroll
        for (int p = 0; p < 6; p++) {
#pragma unroll
            for (int j = 0; j < 2; j++) {
                int col = ac * 96 + p * 16 + j * 8 + 2 * (lane & 3);
                float q0 = qb_s[col], q1 = qb_s[col + 1];
                if (t_a < TT) {
                    float2 v = make_float2(c2[p][j][0] + q0, c2[p][j][1] + q1);
                    *(float2*)(g_scores + (((size_t)b * TT + t_a) * NH + n) * AA + col) = v;
                }
                if (t_b < TT) {
                    float2 v = make_float2(c2[p][j][2] + q0, c2[p][j][3] + q1);
                    *(float2*)(g_scores + (((size_t)b * TT + t_b) * NH + n) * AA + col) = v;
                }
            }
        }
    }
}

// ---------------- K4a: pool partials (8-way T split, __expf) ---------------
__global__ __launch_bounds__(192) void k_pool_part(const float* __restrict__ ht) {
    int bn = blockIdx.x;
    int sp = blockIdx.y;
    int b = bn >> 3, n = bn & 7;
    int a = threadIdx.x;
    const int CH = TT / 8;  // 250
    int ts = sp * CH, te = ts + CH;

    float m = -1e30f, Z = 0.f, S1 = 0.f, S2 = 0.f;
    const float* sc = g_scores + ((size_t)b * TT * NH + n) * AA + a;
    const float* vp = ht + (size_t)b * TT * CC + n * DD + a;
    for (int t = ts; t < te; t++) {
        float s = sc[(size_t)t * NH * AA];
        float v = vp[(size_t)t * CC];
        float nm = fmaxf(m, s);
        float cc = __expf(m - nm);
        float wv = __expf(s - nm);
        Z = Z * cc + wv;
        S1 = S1 * cc + wv * v;
        S2 = S2 * cc + wv * v * v;
        m = nm;
    }
    g_pp[((size_t)bn * 8 + sp) * AA + a] = make_float4(m, Z, S1, S2);
}

// ---------------- K4b: merge partials -> output ----------------------------
__global__ __launch_bounds__(192) void k_pool_merge(float* __restrict__ out) {
    int bn = blockIdx.x;
    int b = bn >> 3, n = bn & 7;
    int a = threadIdx.x;

    float4 p[8];
#pragma unroll
    for (int s = 0; s < 8; s++) p[s] = g_pp[((size_t)bn * 8 + s) * AA + a];
    float M = p[0].x;
#pragma unroll
    for (int s = 1; s < 8; s++) M = fmaxf(M, p[s].x);
    float Zt = 0.f, S1t = 0.f, S2t = 0.f;
#pragma unroll
    for (int s = 0; s < 8; s++) {
        float c = __expf(p[s].x - M);
        Zt += p[s].y * c; S1t += p[s].z * c; S2t += p[s].w * c;
    }
    float mu = S1t / Zt;
    float ex2 = S2t / Zt;
    float rh = sqrtf(fmaxf(ex2 - mu * mu, 1e-9f));
    out[(size_t)b * (2 * CC) + n * DD + a] = mu;
    out[(size_t)b * (2 * CC) + CC + n * DD + a] = rh;
}

// ---------------- launcher ------------------------------------------------
extern "C" void kernel_launch(void* const* d_in, const int* in_sizes, int n_in,
                              void* d_out, int out_size) {
    const float* ht       = (const float*)d_in[0];
    const float* k_proj_W = (const float*)d_in[1];
    const float* query    = (const float*)d_in[2];
    const float* uk_W     = (const float*)d_in[3];
    const float* u_q1W    = (const float*)d_in[4];
    const float* u_q2     = (const float*)d_in[5];
    const float* vhq      = (const float*)d_in[6];
    const float* vhk      = (const float*)d_in[7];
    const float* vcq      = (const float*)d_in[8];
    const float* vck      = (const float*)d_in[9];
    const float* k_proj_b = (const float*)d_in[10];
    const float* q_b      = (const float*)d_in[11];
    const float* u_q1b    = (const float*)d_in[12];
    const float* bnc_g    = (const float*)d_in[13];
    const float* bnc_b    = (const float*)d_in[14];
    const float* bnc_m    = (const float*)d_in[15];
    const float* bnc_v    = (const float*)d_in[16];
    const float* bnk_g    = (const float*)d_in[17];
    const float* bnk_b    = (const float*)d_in[18];
    const float* bnk_m    = (const float*)d_in[19];
    const float* bnk_v    = (const float*)d_in[20];
    float* out = (float*)d_out;

    static int smem_set = 0;
    if (!smem_set) {
        cudaFuncSetAttribute(k_scores_mma,
                             cudaFuncAttributeMaxDynamicSharedMemorySize, SMEM_SC);
        smem_set = 1;
    }

    dim3 gs(CC / 128, BB);
    dim3 bs(128, 8);
    k_stats<<<gs, bs>>>(ht);

    dim3 gt(48, NH), bt(32, 8);
    k_prepw<<<gt, bt>>>(k_proj_W);
    k_prepq<<<gt, bt>>>(query);
    dim3 gq(8, NH);
    k_qdot<<<gq, 256>>>(query, vhq, vcq);

    dim3 ga(8, NH);
    k_ctx_a<<<ga, 256>>>(uk_W, u_q1W, u_q1b, bnc_g, bnc_b, bnc_m, bnc_v);
    dim3 gb(6, NH);
    k_ctx_b<<<gb, 256>>>(u_q2);
    k_ctx_c<<<BB * NH, 256>>>(vck);

    dim3 gsc(16, BB * NH);
    k_scores_mma<<<gsc, 256, SMEM_SC>>>(ht, k_proj_b, bnk_g, bnk_b, bnk_m, bnk_v,
                                        vhk, q_b);

    dim3 gp(BB * NH, 8);
    k_pool_part<<<gp, AA>>>(ht);
    k_pool_merge<<<BB * NH, AA>>>(out);
}

// round 8
// speedup vs baseline: 4.4797x; 1.0054x over previous
#include <cuda_runtime.h>
#include <cuda_bf16.h>
#include <math.h>
#include <stdint.h>

// Problem constants
#define BB 16
#define TT 2000
#define CC 1536
#define NH 8
#define DD 192
#define QQ 256
#define AA 192

// ===================== warp-MMA helpers (sm_80+ baseline, no 'a' gate) =====
__device__ __forceinline__ uint32_t smem_u32(const void* p) {
    uint32_t a;
    asm("{ .reg .u64 t; cvta.to.shared.u64 t, %1; cvt.u32.u64 %0, t; }"
        : "=r"(a) : "l"(p));
    return a;
}
__device__ __forceinline__ void ldsm_x4(uint32_t r[4], uint32_t addr) {
    asm volatile("ldmatrix.sync.aligned.m8n8.x4.shared.b16 {%0,%1,%2,%3}, [%4];"
                 : "=r"(r[0]), "=r"(r[1]), "=r"(r[2]), "=r"(r[3]) : "r"(addr));
}
__device__ __forceinline__ void mma_bf16(float c[4], const uint32_t a[4],
                                         uint32_t b0, uint32_t b1) {
    asm volatile("mma.sync.aligned.m16n8k16.row.col.f32.bf16.bf16.f32 "
                 "{%0,%1,%2,%3}, {%4,%5,%6,%7}, {%8,%9}, {%0,%1,%2,%3};"
                 : "+f"(c[0]), "+f"(c[1]), "+f"(c[2]), "+f"(c[3])
                 : "r"(a[0]), "r"(a[1]), "r"(a[2]), "r"(a[3]), "r"(b0), "r"(b1));
}
__device__ __forceinline__ uint32_t pack_bf(float lo, float hi) {
    uint32_t r;
    asm("cvt.rn.bf16x2.f32 %0, %1, %2;" : "=r"(r) : "f"(hi), "f"(lo));
    return r;
}
__device__ __forceinline__ float bflo(uint32_t u) { return __uint_as_float(u << 16); }
__device__ __forceinline__ float bfhi(uint32_t u) { return __uint_as_float(u & 0xffff0000u); }
__device__ __forceinline__ float tanha(float x) {
    float r; asm("tanh.approx.f32 %0, %1;" : "=f"(r) : "f"(x)); return r;
}
#define CP_ASYNC16(dst, src) \
    asm volatile("cp.async.cg.shared.global [%0], [%1], 16;" :: "r"(dst), "l"(src))
#define CP_COMMIT() asm volatile("cp.async.commit_group;" ::: "memory")
#define CP_WAIT0() asm volatile("cp.async.wait_group 0;" ::: "memory")
#define CP_WAIT1() asm volatile("cp.async.wait_group 1;" ::: "memory")

// ---------------- scratch (device globals: no allocations allowed) --------
__device__ float g_c[BB * CC * 2];
__device__ float g_hck[BB * NH * QQ];
__device__ float g_t1[BB * NH * QQ];
__device__ float g_cq2[BB * NH * AA];
__device__ float g_vcqsum[NH * AA];
__device__ float g_ckdot[BB * NH];
__device__ float g_qdotp[NH * 8];
__device__ float g_qT[NH * AA * QQ];                          // query^T [n][a][q]
__device__ __nv_bfloat16 g_w1t[NH * QQ * DD];                 // W1^T [n][q][d] bf16
__device__ __nv_bfloat16 g_hcqT[(size_t)BB * NH * AA * QQ];   // hcq^T/sqrt(Q) [bn][a][q]
__device__ float4 g_pp[BB * NH * 16 * AA];                    // pool partials per tile

// ---------------- K1: mean/std over time ----------------------------------
__global__ void k_stats(const float* __restrict__ ht) {
    int b = blockIdx.y;
    int ch = blockIdx.x * 128 + threadIdx.x;
    int ty = threadIdx.y;
    float s = 0.f, s2 = 0.f;
    const float* p = ht + (size_t)b * TT * CC + ch;
    for (int t = ty; t < TT; t += 8) {
        float v = p[(size_t)t * CC];
        s += v; s2 += v * v;
    }
    __shared__ float sh0[8][128];
    __shared__ float sh1[8][128];
    sh0[ty][threadIdx.x] = s;
    sh1[ty][threadIdx.x] = s2;
    __syncthreads();
    if (ty == 0) {
        for (int j = 1; j < 8; j++) { s += sh0[j][threadIdx.x]; s2 += sh1[j][threadIdx.x]; }
        float mean = s * (1.f / TT);
        float var = (s2 - (float)TT * mean * mean) * (1.f / (TT - 1));
        float sd = sqrtf(fmaxf(var, 0.f));
        g_c[((size_t)b * CC + ch) * 2 + 0] = mean;
        g_c[((size_t)b * CC + ch) * 2 + 1] = sd;
    }
}

// ---------------- K0: qdot partials + vcq_sum ------------------------------
__global__ void k_qdot(const float* __restrict__ query, const float* __restrict__ vhq,
                       const float* __restrict__ vcq) {
    int s = blockIdx.x;     // 0..7 slice
    int n = blockIdx.y;
    int tid = threadIdx.x;
    float acc = 0.f;
    int base = s * (AA * QQ / 8);
    for (int ii = tid; ii < AA * QQ / 8; ii += 256) {
        int i = base + ii;
        int a = i >> 8, q = i & 255;
        acc += query[(n * QQ + q) * AA + a] * vhq[n * AA * QQ + i];
    }
    __shared__ float red[256];
    red[tid] = acc;
    __syncthreads();
    for (int off = 128; off > 0; off >>= 1) {
        if (tid < off) red[tid] += red[tid + off];
        __syncthreads();
    }
    if (tid == 0) g_qdotp[n * 8 + s] = red[0];

    int w = tid >> 5, lane = tid & 31;
    for (int r = w; r < AA / 8; r += 8) {
        int a = s * (AA / 8) + r;
        const float* vp = vcq + ((size_t)n * AA + a) * QQ;
        float sum = 0.f;
        for (int q = lane; q < QQ; q += 32) sum += vp[q];
#pragma unroll
        for (int o = 16; o > 0; o >>= 1) sum += __shfl_down_sync(0xffffffffu, sum, o);
        if (lane == 0) g_vcqsum[n * AA + a] = sum;
    }
}

// ---------------- prep: W1^T -> bf16 (tiled transpose) ---------------------
__global__ void k_prepw(const float* __restrict__ W1) {
    int n = blockIdx.y;
    int tile = blockIdx.x;
    int d0 = (tile % 6) * 32, q0 = (tile / 6) * 32;
    int tx = threadIdx.x, ty = threadIdx.y;
    __shared__ float tl[32][33];
#pragma unroll
    for (int j = 0; j < 4; j++)
        tl[ty + j * 8][tx] = W1[((size_t)n * DD + d0 + ty + j * 8) * QQ + q0 + tx];
    __syncthreads();
#pragma unroll
    for (int j = 0; j < 4; j++)
        g_w1t[((size_t)n * QQ + q0 + ty + j * 8) * DD + d0 + tx] =
            __float2bfloat16_rn(tl[tx][ty + j * 8]);
}

// ---------------- prep: query^T fp32 (tiled transpose) ---------------------
__global__ void k_prepq(const float* __restrict__ query) {
    int n = blockIdx.y;
    int tile = blockIdx.x;
    int a0 = (tile % 6) * 32, q0 = (tile / 6) * 32;
    int tx = threadIdx.x, ty = threadIdx.y;
    __shared__ float tl[32][33];
#pragma unroll
    for (int j = 0; j < 4; j++)
        tl[ty + j * 8][tx] = query[((size_t)n * QQ + q0 + ty + j * 8) * AA + a0 + tx];
    __syncthreads();
#pragma unroll
    for (int j = 0; j < 4; j++)
        g_qT[((size_t)n * AA + a0 + ty + j * 8) * QQ + q0 + tx] = tl[tx][ty + j * 8];
}

// ---------------- ctx-a: hck + t1 for all 16 b per block -------------------
__global__ __launch_bounds__(256) void k_ctx_a(
        const float* __restrict__ uk_W, const float* __restrict__ u_q1W,
        const float* __restrict__ u_q1b,
        const float* __restrict__ bnc_g, const float* __restrict__ bnc_b,
        const float* __restrict__ bnc_m, const float* __restrict__ bnc_v) {
    int n = blockIdx.y, qt = blockIdx.x;
    int tid = threadIdx.x;
    int qi = tid & 31, sl = tid >> 5;
    int q = qt * 32 + qi;

    __shared__ float c_sh[16 * 384];
    __shared__ float part[8 * 16 * 33];

    for (int i = tid; i < 16 * 384; i += 256) {
        int b = i / 384, l = i - b * 384;
        c_sh[i] = g_c[((size_t)b * CC + n * DD) * 2 + l];
    }
    __syncthreads();

    float ak[16], aq[16];
#pragma unroll
    for (int b = 0; b < 16; b++) { ak[b] = 0.f; aq[b] = 0.f; }
    {
        const float* uk = uk_W + ((size_t)n * 384) * QQ + q;
        const float* u1 = u_q1W + ((size_t)n * 384) * QQ + q;
        int l0 = sl * 48;
        for (int l = l0; l < l0 + 48; l++) {
            float wk = uk[(size_t)l * QQ];
            float w1 = u1[(size_t)l * QQ];
            const float* cb = c_sh + l;
#pragma unroll
            for (int b = 0; b < 16; b++) {
                float cv = cb[b * 384];
                ak[b] = fmaf(cv, wk, ak[b]);
                aq[b] = fmaf(cv, w1, aq[b]);
            }
        }
    }

#pragma unroll
    for (int b = 0; b < 16; b++) part[(sl * 16 + b) * 33 + qi] = ak[b];
    __syncthreads();
    {
        int bp = tid >> 5;
        float s0 = 0.f, s1 = 0.f;
#pragma unroll
        for (int s = 0; s < 8; s++) {
            s0 += part[(s * 16 + bp) * 33 + qi];
            s1 += part[(s * 16 + bp + 8) * 33 + qi];
        }
        g_hck[((size_t)(bp * NH + n)) * QQ + q] = s0;
        g_hck[((size_t)((bp + 8) * NH + n)) * QQ + q] = s1;
    }
    __syncthreads();

#pragma unroll
    for (int b = 0; b < 16; b++) part[(sl * 16 + b) * 33 + qi] = aq[b];
    __syncthreads();
    {
        int bp = tid >> 5;
        float s0 = 0.f, s1 = 0.f;
#pragma unroll
        for (int s = 0; s < 8; s++) {
            s0 += part[(s * 16 + bp) * 33 + qi];
            s1 += part[(s * 16 + bp + 8) * 33 + qi];
        }
        float bias = u_q1b[n * QQ + q];
        float grs = bnc_g[q] * rsqrtf(bnc_v[q] + 1e-5f);
        float beta = bnc_b[q] - grs * bnc_m[q];
        float r0 = fmaxf(s0 + bias, 0.f);
        float r1 = fmaxf(s1 + bias, 0.f);
        g_t1[((size_t)(bp * NH + n)) * QQ + q] = tanhf(fmaf(grs, r0, beta));
        g_t1[((size_t)((bp + 8) * NH + n)) * QQ + q] = tanhf(fmaf(grs, r1, beta));
    }
}

// ---------------- ctx-b: cq2 = t1 @ u_q2 for all 16 b per block ------------
__global__ __launch_bounds__(256) void k_ctx_b(const float* __restrict__ u_q2) {
    int n = blockIdx.y, at = blockIdx.x;
    int tid = threadIdx.x;
    int ai = tid & 31, msl = tid >> 5;
    int a = at * 32 + ai;

    __shared__ float t1_sh[16 * 256];
    __shared__ float part[8 * 16 * 33];

    for (int i = tid; i < 16 * 256; i += 256) {
        int b = i >> 8, m = i & 255;
        t1_sh[i] = g_t1[((size_t)(b * NH + n)) * QQ + m];
    }
    __syncthreads();

    float acc[16];
#pragma unroll
    for (int b = 0; b < 16; b++) acc[b] = 0.f;
    {
        const float* u2 = u_q2 + (size_t)n * QQ * AA + a;
        int m0 = msl * 32;
        for (int m = m0; m < m0 + 32; m++) {
            float w = u2[(size_t)m * AA];
            const float* tb = t1_sh + m;
#pragma unroll
            for (int b = 0; b < 16; b++)
                acc[b] = fmaf(tb[b * 256], w, acc[b]);
        }
    }
#pragma unroll
    for (int b = 0; b < 16; b++) part[(msl * 16 + b) * 33 + ai] = acc[b];
    __syncthreads();
    {
        int bp = tid >> 5;
        float s0 = 0.f, s1 = 0.f;
#pragma unroll
        for (int s = 0; s < 8; s++) {
            s0 += part[(s * 16 + bp) * 33 + ai];
            s1 += part[(s * 16 + bp + 8) * 33 + ai];
        }
        g_cq2[((size_t)(bp * NH + n)) * AA + a] = s0;
        g_cq2[((size_t)((bp + 8) * NH + n)) * AA + a] = s1;
    }
}

// ---------------- ctx-c: scalars + hcqT write (coalesced) ------------------
__global__ __launch_bounds__(256) void k_ctx_c(const float* __restrict__ vck) {
    int bn = blockIdx.x;
    int n = bn & 7;
    int tid = threadIdx.x;

    __shared__ float cq2_sh[AA];
    __shared__ float red[256];
    __shared__ float lamq_sh;

    if (tid < AA) cq2_sh[tid] = g_cq2[(size_t)bn * AA + tid];

    red[tid] = g_hck[(size_t)bn * QQ + tid] * vck[n * QQ + tid];
    __syncthreads();
    for (int off = 128; off > 0; off >>= 1) {
        if (tid < off) red[tid] += red[tid + off];
        __syncthreads();
    }
    if (tid == 0) g_ckdot[bn] = red[0];
    __syncthreads();

    red[tid] = (tid < AA) ? cq2_sh[tid] * g_vcqsum[n * AA + tid] : 0.f;
    __syncthreads();
    for (int off = 128; off > 0; off >>= 1) {
        if (tid < off) red[tid] += red[tid + off];
        __syncthreads();
    }
    if (tid == 0) {
        float qd = 0.f;
#pragma unroll
        for (int k = 0; k < 8; k++) qd += g_qdotp[n * 8 + k];
        lamq_sh = 1.f / (1.f + __expf(-(qd + red[0])));
    }
    __syncthreads();

    float lq = lamq_sh;
    const float inv_sq = 1.f / 16.f;
    const float* qtp = g_qT + (size_t)n * AA * QQ + tid;
    __nv_bfloat16* op = g_hcqT + (size_t)bn * AA * QQ + tid;
#pragma unroll 4
    for (int a = 0; a < AA; a++) {
        float qv = qtp[(size_t)a * QQ];
        float v = (fmaf(lq, cq2_sh[a] - qv, qv)) * inv_sq;
        op[(size_t)a * QQ] = __float2bfloat16_rn(v);
    }
}

// ---------------- K3: fused scores + softmax-partial kernel ----------------
#define XS_STRIDE 200
#define HK_STRIDE 264
#define SS_STRIDE 100          // fp32 score chunk stride (floats)
#define SM_XS 0
#define SM_HK 51200
#define SM_W1A 118784
#define SM_W1B 144384
#define SM_AUX 169984
#define AXH_HCK  (SM_AUX + 0)
#define AXH_KBV  (SM_AUX + 1024)
#define AXH_GRS  (SM_AUX + 2048)
#define AXH_BETA (SM_AUX + 3072)
#define AXH_VHK  (SM_AUX + 4096)
#define AXH_QB   (SM_AUX + 5120)
#define AXH_LAM  (SM_AUX + 6144)
#define SMEM_SC  (SM_AUX + 6656)

__global__ __launch_bounds__(256) void k_scores_mma(
        const float* __restrict__ ht, const float* __restrict__ kb,
        const float* __restrict__ bg, const float* __restrict__ bbias,
        const float* __restrict__ bm, const float* __restrict__ bv,
        const float* __restrict__ vhk, const float* __restrict__ qb) {
    extern __shared__ char smem[];
    uint32_t sb = smem_u32(smem);
    int tid = threadIdx.x;
    int w = tid >> 5, lane = tid & 31;
    int bn = blockIdx.y;
    int b = bn >> 3, n = bn & 7;
    int t0 = blockIdx.x * 128;

    // kick off W1 chunk 0 async load immediately
    {
        const uint4* wsrc = (const uint4*)(g_w1t + (size_t)n * QQ * DD);
#pragma unroll
        for (int it = 0; it < 6; it++) {
            int idx = it * 256 + tid;
            int row = idx / 24, c8 = idx - row * 24;
            CP_ASYNC16(sb + SM_W1A + (row * XS_STRIDE + c8 * 8) * 2, wsrc + idx);
        }
        CP_COMMIT();
    }

    // aux constant arrays
    {
        int i = tid;
        float g = bg[i];
        float grs = g * rsqrtf(bv[i] + 1e-5f);
        ((float*)(smem + AXH_GRS))[i] = grs;
        ((float*)(smem + AXH_BETA))[i] = bbias[i] - grs * bm[i];
        ((float*)(smem + AXH_HCK))[i] = g_hck[(size_t)bn * QQ + i];
        ((float*)(smem + AXH_KBV))[i] = kb[n * QQ + i];
        ((float*)(smem + AXH_VHK))[i] = vhk[n * QQ + i];
        if (i < AA) ((float*)(smem + AXH_QB))[i] = qb[n * AA + i];
    }

    // ---- load x tile (fp32 -> bf16), rows padded with zeros past TT ----
    {
        const float* xb = ht + ((size_t)b * TT + t0) * CC + n * DD;
        for (int it = 0; it < 24; it++) {
            int idx = it * 256 + tid;
            int row = idx / 48, c4 = idx - row * 48;
            float4 v = make_float4(0.f, 0.f, 0.f, 0.f);
            if (t0 + row < TT) v = *(const float4*)(xb + (size_t)row * CC + c4 * 4);
            uint2 pk = make_uint2(pack_bf(v.x, v.y), pack_bf(v.z, v.w));
            *(uint2*)(smem + SM_XS + (row * XS_STRIDE + c4 * 4) * 2) = pk;
        }
    }

    uint32_t abase = sb + SM_XS + ((w * 16 + (lane & 15)) * XS_STRIDE + (lane >> 4) * 8) * 2;
    uint32_t boff_w1 = (((lane >> 4) * 8 + (lane & 7)) * XS_STRIDE + ((lane >> 3) & 1) * 8) * 2;

    // ---- GEMM1 over 4 q-chunks of 64, double-buffered W1; lambda in regs --
    float lam0 = 0.f, lam1 = 0.f;
    for (int qc = 0; qc < 4; qc++) {
        if (qc < 3) {
            int buf = ((qc + 1) & 1) ? SM_W1B : SM_W1A;
            const uint4* wsrc = (const uint4*)(g_w1t + ((size_t)n * QQ + (qc + 1) * 64) * DD);
#pragma unroll
            for (int it = 0; it < 6; it++) {
                int idx = it * 256 + tid;
                int row = idx / 24, c8 = idx - row * 24;
                CP_ASYNC16(sb + buf + (row * XS_STRIDE + c8 * 8) * 2, wsrc + idx);
            }
            CP_COMMIT();
            CP_WAIT1();
        } else {
            CP_WAIT0();
        }
        __syncthreads();

        uint32_t bbase = sb + ((qc & 1) ? SM_W1B : SM_W1A) + boff_w1;

        float c[4][2][4];
#pragma unroll
        for (int p = 0; p < 4; p++)
#pragma unroll
            for (int j = 0; j < 2; j++)
#pragma unroll
                for (int e = 0; e < 4; e++) c[p][j][e] = 0.f;

        for (int kk = 0; kk < 12; kk++) {
            uint32_t a[4];
            ldsm_x4(a, abase + kk * 32);
#pragma unroll
            for (int p = 0; p < 4; p++) {
                uint32_t bf[4];
                ldsm_x4(bf, bbase + p * 16 * XS_STRIDE * 2 + kk * 32);
                mma_bf16(c[p][0], a, bf[0], bf[1]);
                mma_bf16(c[p][1], a, bf[2], bf[3]);
            }
        }

        const float* vhk_s = (const float*)(smem + AXH_VHK);
        int r0 = w * 16 + (lane >> 2);
#pragma unroll
        for (int p = 0; p < 4; p++) {
#pragma unroll
            for (int j = 0; j < 2; j++) {
                int col = qc * 64 + p * 16 + j * 8 + 2 * (lane & 3);
                float v0 = vhk_s[col], v1 = vhk_s[col + 1];
                lam0 += c[p][j][0] * v0 + c[p][j][1] * v1;
                lam1 += c[p][j][2] * v0 + c[p][j][3] * v1;
                *(uint32_t*)(smem + SM_HK + (r0 * HK_STRIDE + col) * 2) =
                    pack_bf(c[p][j][0], c[p][j][1]);
                *(uint32_t*)(smem + SM_HK + ((r0 + 8) * HK_STRIDE + col) * 2) =
                    pack_bf(c[p][j][2], c[p][j][3]);
            }
        }
        __syncthreads();
    }

    // prefetch hcq chunk 0 into XS region (xs dead after GEMM1)
    {
        const uint4* hs = (const uint4*)(g_hcqT + (size_t)bn * AA * QQ);
#pragma unroll
        for (int it = 0; it < 12; it++) {
            int idx = it * 256 + tid;
            int row = idx / 32, c8 = idx - row * 32;
            CP_ASYNC16(sb + SM_XS + (row * HK_STRIDE + c8 * 8) * 2, hs + idx);
        }
        CP_COMMIT();
    }

    // lambda finalize
    lam0 += __shfl_xor_sync(0xffffffffu, lam0, 1);
    lam0 += __shfl_xor_sync(0xffffffffu, lam0, 2);
    lam1 += __shfl_xor_sync(0xffffffffu, lam1, 1);
    lam1 += __shfl_xor_sync(0xffffffffu, lam1, 2);
    {
        float ckd = g_ckdot[bn];
        if ((lane & 3) == 0) {
            float* lam_sh = (float*)(smem + AXH_LAM);
            lam_sh[w * 16 + (lane >> 2)] = 1.f / (1.f + __expf(-(lam0 + ckd)));
            lam_sh[w * 16 + (lane >> 2) + 8] = 1.f / (1.f + __expf(-(lam1 + ckd)));
        }
    }
    __syncthreads();

    // ---- activation in place (overlaps hcq chunk0 cp.async) ----
    {
        int row = w * 16 + (lane >> 1);
        int cb = (lane & 1) * 128;
        float lam = ((const float*)(smem + AXH_LAM))[row];
        const float* hck_s = (const float*)(smem + AXH_HCK);
        const float* kbv_s = (const float*)(smem + AXH_KBV);
        const float* grs_s = (const float*)(smem + AXH_GRS);
        const float* bet_s = (const float*)(smem + AXH_BETA);
        uint32_t* hp = (uint32_t*)(smem + SM_HK + (row * HK_STRIDE + cb) * 2);
        for (int j = 0; j < 16; j++) {
            uint4 v = *(uint4*)(hp + j * 4);
            uint32_t* vr = (uint32_t*)&v;
#pragma unroll
            for (int e = 0; e < 4; e++) {
                int c0 = cb + j * 8 + 2 * e;
                float h0 = bflo(vr[e]), h1 = bfhi(vr[e]);
                float m0 = fmaf(lam, hck_s[c0] - h0, h0) + kbv_s[c0];
                float m1 = fmaf(lam, hck_s[c0 + 1] - h1, h1) + kbv_s[c0 + 1];
                m0 = fmaxf(m0, 0.f); m1 = fmaxf(m1, 0.f);
                float a0 = tanha(fmaf(grs_s[c0], m0, bet_s[c0]));
                float a1 = tanha(fmaf(grs_s[c0 + 1], m1, bet_s[c0 + 1]));
                vr[e] = pack_bf(a0, a1);
            }
            *(uint4*)(hp + j * 4) = v;
        }
    }

    // ---- GEMM2 over 2 a-chunks of 96; fragments -> fp32 smem --------------
    uint32_t abase2 = sb + SM_HK + ((w * 16 + (lane & 15)) * HK_STRIDE + (lane >> 4) * 8) * 2;
    uint32_t boff_hcq = (((lane >> 4) * 8 + (lane & 7)) * HK_STRIDE + ((lane >> 3) & 1) * 8) * 2;
    int r0 = w * 16 + (lane >> 2);

    for (int ac = 0; ac < 2; ac++) {
        if (ac == 0) {
            const uint4* hs = (const uint4*)(g_hcqT + ((size_t)bn * AA + 96) * QQ);
#pragma unroll
            for (int it = 0; it < 12; it++) {
                int idx = it * 256 + tid;
                int row = idx / 32, c8 = idx - row * 32;
                CP_ASYNC16(sb + SM_W1A + (row * HK_STRIDE + c8 * 8) * 2, hs + idx);
            }
            CP_COMMIT();
            CP_WAIT1();
        } else {
            CP_WAIT0();
        }
        __syncthreads();

        uint32_t bbase2 = sb + (ac ? SM_W1A : SM_XS) + boff_hcq;

        float c2[6][2][4];
#pragma unroll
        for (int p = 0; p < 6; p++)
#pragma unroll
            for (int j = 0; j < 2; j++)
#pragma unroll
                for (int e = 0; e < 4; e++) c2[p][j][e] = 0.f;

        for (int kk = 0; kk < 16; kk++) {
            uint32_t a[4];
            ldsm_x4(a, abase2 + kk * 32);
#pragma unroll
            for (int p = 0; p < 6; p++) {
                uint32_t bf[4];
                ldsm_x4(bf, bbase2 + p * 16 * HK_STRIDE * 2 + kk * 32);
                mma_bf16(c2[p][0], a, bf[0], bf[1]);
                mma_bf16(c2[p][1], a, bf[2], bf[3]);
            }
        }

        __syncthreads();   // all ldmatrix reads of this chunk's B-region done
        float* sdst = (float*)(smem + (ac ? SM_W1A : SM_XS));
#pragma unroll
        for (int p = 0; p < 6; p++) {
#pragma unroll
            for (int j = 0; j < 2; j++) {
                int col = p * 16 + j * 8 + 2 * (lane & 3);   // local 0..95
                *(float2*)(sdst + r0 * SS_STRIDE + col) =
                    make_float2(c2[p][j][0], c2[p][j][1]);
                *(float2*)(sdst + (r0 + 8) * SS_STRIDE + col) =
                    make_float2(c2[p][j][2], c2[p][j][3]);
            }
        }
    }
    __syncthreads();

    // ---- fused softmax partials: thread == a (192 active) -----------------
    if (tid < AA) {
        int a = tid;
        const float* ssm = (a < 96) ? (const float*)(smem + SM_XS)
                                    : (const float*)(smem + SM_W1A);
        int acol = (a < 96) ? a : (a - 96);
        float qbv = ((const float*)(smem + AXH_QB))[a];
        int tmax = TT - t0; if (tmax > 128) tmax = 128;

        float M = -1e30f;
        for (int t = 0; t < tmax; t++)
            M = fmaxf(M, ssm[t * SS_STRIDE + acol]);
        M += qbv;

        float Z = 0.f, S1 = 0.f, S2 = 0.f;
        const float* vp = ht + ((size_t)b * TT + t0) * CC + n * DD + a;
#pragma unroll 4
        for (int t = 0; t < tmax; t++) {
            float s = ssm[t * SS_STRIDE + acol] + qbv;
            float wv = __expf(s - M);
            float v = vp[(size_t)t * CC];
            Z += wv; S1 += wv * v; S2 += wv * v * v;
        }
        g_pp[((size_t)bn * 16 + blockIdx.x) * AA + a] = make_float4(M, Z, S1, S2);
    }
}

// ---------------- K4: merge 16 tile partials -> output ---------------------
__global__ __launch_bounds__(192) void k_pool_merge(float* __restrict__ out) {
    int bn = blockIdx.x;
    int b = bn >> 3, n = bn & 7;
    int a = threadIdx.x;

    const float4* pp = g_pp + (size_t)bn * 16 * AA + a;
    float M = -1e30f;
#pragma unroll
    for (int s = 0; s < 16; s++) M = fmaxf(M, pp[s * AA].x);
    float Zt = 0.f, S1t = 0.f, S2t = 0.f;
#pragma unroll
    for (int s = 0; s < 16; s++) {
        float4 p = pp[s * AA];
        float c = __expf(p.x - M);
        Zt += p.y * c; S1t += p.z * c; S2t += p.w * c;
    }
    float mu = S1t / Zt;
    float ex2 = S2t / Zt;
    float rh = sqrtf(fmaxf(ex2 - mu * mu, 1e-9f));
    out[(size_t)b * (2 * CC) + n * DD + a] = mu;
    out[(size_t)b * (2 * CC) + CC + n * DD + a] = rh;
}

// ---------------- launcher ------------------------------------------------
extern "C" void kernel_launch(void* const* d_in, const int* in_sizes, int n_in,
                              void* d_out, int out_size) {
    const float* ht       = (const float*)d_in[0];
    const float* k_proj_W = (const float*)d_in[1];
    const float* query    = (const float*)d_in[2];
    const float* uk_W     = (const float*)d_in[3];
    const float* u_q1W    = (const float*)d_in[4];
    const float* u_q2     = (const float*)d_in[5];
    const float* vhq      = (const float*)d_in[6];
    const float* vhk      = (const float*)d_in[7];
    const float* vcq      = (const float*)d_in[8];
    const float* vck      = (const float*)d_in[9];
    const float* k_proj_b = (const float*)d_in[10];
    const float* q_b      = (const float*)d_in[11];
    const float* u_q1b    = (const float*)d_in[12];
    const float* bnc_g    = (const float*)d_in[13];
    const float* bnc_b    = (const float*)d_in[14];
    const float* bnc_m    = (const float*)d_in[15];
    const float* bnc_v    = (const float*)d_in[16];
    const float* bnk_g    = (const float*)d_in[17];
    const float* bnk_b    = (const float*)d_in[18];
    const float* bnk_m    = (const float*)d_in[19];
    const float* bnk_v    = (const float*)d_in[20];
    float* out = (float*)d_out;

    static int smem_set = 0;
    if (!smem_set) {
        cudaFuncSetAttribute(k_scores_mma,
                             cudaFuncAttributeMaxDynamicSharedMemorySize, SMEM_SC);
        smem_set = 1;
    }

    dim3 gs(CC / 128, BB);
    dim3 bs(128, 8);
    k_stats<<<gs, bs>>>(ht);

    dim3 gt(48, NH), bt(32, 8);
    k_prepw<<<gt, bt>>>(k_proj_W);
    k_prepq<<<gt, bt>>>(query);
    dim3 gq(8, NH);
    k_qdot<<<gq, 256>>>(query, vhq, vcq);

    dim3 ga(8, NH);
    k_ctx_a<<<ga, 256>>>(uk_W, u_q1W, u_q1b, bnc_g, bnc_b, bnc_m, bnc_v);
    dim3 gb(6, NH);
    k_ctx_b<<<gb, 256>>>(u_q2);
    k_ctx_c<<<BB * NH, 256>>>(vck);

    dim3 gsc(16, BB * NH);
    k_scores_mma<<<gsc, 256, SMEM_SC>>>(ht, k_proj_b, bnk_g, bnk_b, bnk_m, bnk_v,
                                        vhk, q_b);

    k_pool_merge<<<BB * NH, AA>>>(out);
}